// round 15
// baseline (speedup 1.0000x reference)
#include <cuda_runtime.h>
#include <cuda_bf16.h>
#include <math.h>
#include <stdint.h>

// Problem constants
#define Bc   8
#define Sc   1024
#define Dc   1024
#define Hc   16
#define Mrows (Bc*Sc)      // 8192
#define KROW 2048          // compact split: [hi(1024) | lo(1024)]
#define NHC  32            // 32 half-chunks of 32 K-cols
#define ASEC ((size_t)Mrows*KROW)
#define WSEC ((size_t)Dc*KROW)

// ---------------- scratch (device globals: allocation-free) ----------------
__device__ __nv_bfloat16 g_qs[(size_t)Bc*Hc*Sc*128];
__device__ __nv_bfloat16 g_ks[(size_t)Bc*Hc*Sc*128];
__device__ __nv_bfloat16 g_vs[(size_t)Bc*Hc*Sc*128];
__device__ __nv_bfloat16 g_ap[3*ASEC];
__device__ __nv_bfloat16 g_wp[4*WSEC];
__device__ float g_vbar[Bc*1024];
__device__ float g_vmean[Bc*Hc*64];

__device__ __forceinline__ uint32_t smem_u32(const void* p) {
    uint32_t a;
    asm("{ .reg .u64 t; cvta.to.shared.u64 t, %1; cvt.u32.u64 %0, t; }"
        : "=r"(a) : "l"(p));
    return a;
}

__device__ __forceinline__ uint32_t pack_bf2(float a, float b) {
    __nv_bfloat16 ha = __float2bfloat16(a), hb = __float2bfloat16(b);
    return (uint32_t)__bfloat16_as_ushort(ha) | ((uint32_t)__bfloat16_as_ushort(hb) << 16);
}

// ---------------------------------------------------------------------------
// fp32 -> bf16 compact split conversions
// ---------------------------------------------------------------------------
__device__ __forceinline__ void conv8_core(const float* __restrict__ src,
                                           __nv_bfloat16* __restrict__ dst_hi,
                                           __nv_bfloat16* __restrict__ dst_lo)
{
    float4 x0 = *(const float4*)src;
    float4 x1 = *(const float4*)(src + 4);
    __nv_bfloat16 h0 = __float2bfloat16(x0.x), h1 = __float2bfloat16(x0.y);
    __nv_bfloat16 h2 = __float2bfloat16(x0.z), h3 = __float2bfloat16(x0.w);
    __nv_bfloat16 h4 = __float2bfloat16(x1.x), h5 = __float2bfloat16(x1.y);
    __nv_bfloat16 h6 = __float2bfloat16(x1.z), h7 = __float2bfloat16(x1.w);
    uint4 hv, lv;
    hv.x = (uint32_t)__bfloat16_as_ushort(h0) | ((uint32_t)__bfloat16_as_ushort(h1) << 16);
    hv.y = (uint32_t)__bfloat16_as_ushort(h2) | ((uint32_t)__bfloat16_as_ushort(h3) << 16);
    hv.z = (uint32_t)__bfloat16_as_ushort(h4) | ((uint32_t)__bfloat16_as_ushort(h5) << 16);
    hv.w = (uint32_t)__bfloat16_as_ushort(h6) | ((uint32_t)__bfloat16_as_ushort(h7) << 16);
    lv.x = pack_bf2(x0.x - __bfloat162float(h0), x0.y - __bfloat162float(h1));
    lv.y = pack_bf2(x0.z - __bfloat162float(h2), x0.w - __bfloat162float(h3));
    lv.z = pack_bf2(x1.x - __bfloat162float(h4), x1.y - __bfloat162float(h5));
    lv.w = pack_bf2(x1.z - __bfloat162float(h6), x1.w - __bfloat162float(h7));
    *(uint4*)dst_hi = hv;
    *(uint4*)dst_lo = lv;
}

__global__ __launch_bounds__(256) void conv_a3(
    const float* __restrict__ q, const float* __restrict__ k,
    const float* __restrict__ v, __nv_bfloat16* __restrict__ Y)
{
    const float* X = (blockIdx.y == 0) ? q : (blockIdx.y == 1) ? k : v;
    int i = blockIdx.x * 256 + threadIdx.x;
    int r = i >> 7;
    int c8 = (i & 127) << 3;
    size_t base = (size_t)blockIdx.y * ASEC + (size_t)r * KROW;
    conv8_core(X + (size_t)r * 1024 + c8, Y + base + c8, Y + base + 1024 + c8);
}

__global__ __launch_bounds__(256) void conv_w_all(
    const float* __restrict__ W0, const float* __restrict__ W1,
    const float* __restrict__ W2, const float* __restrict__ W3,
    __nv_bfloat16* __restrict__ Y)
{
    const float* X = (blockIdx.y == 0) ? W0 : (blockIdx.y == 1) ? W1
                   : (blockIdx.y == 2) ? W2 : W3;
    int i = blockIdx.x * 256 + threadIdx.x;
    int r = i >> 7;
    int c8 = (i & 127) << 3;
    size_t base = (size_t)blockIdx.y * WSEC + (size_t)r * KROW;
    conv8_core(X + (size_t)r * 1024 + c8, Y + base + c8, Y + base + 1024 + c8);
}

// ---------------------------------------------------------------------------
// vbar[b,k] = mean_s v[b,s,k]  — 512 CTAs
// ---------------------------------------------------------------------------
__global__ __launch_bounds__(256) void vbar_kernel(
    const float* __restrict__ v, float* __restrict__ vbar)
{
    __shared__ float sm[256];
    int b  = blockIdx.x >> 6;
    int cb = (blockIdx.x & 63) * 16;
    int tid = threadIdx.x;
    int col = tid & 15;
    int rg  = tid >> 4;
    const float* src = v + (size_t)b * 1024 * 1024 + cb;
    float s = 0.f;
    for (int r = rg; r < 1024; r += 16)
        s += src[(size_t)r * 1024 + col];
    sm[tid] = s;
    __syncthreads();
    if (rg < 8)  sm[tid] += sm[tid + 128];
    __syncthreads();
    if (rg < 4)  sm[tid] += sm[tid + 64];
    __syncthreads();
    if (rg < 2)  sm[tid] += sm[tid + 32];
    __syncthreads();
    if (rg == 0) {
        float r = sm[tid] + sm[tid + 16];
        vbar[b * 1024 + cb + col] = r * (1.0f / 1024.0f);
    }
}

__global__ __launch_bounds__(256) void vmean_small(
    const float* __restrict__ Wv, const float* __restrict__ vbar,
    float* __restrict__ vmean)
{
    int bh = blockIdx.x;
    int b = bh >> 4, h = bh & 15;
    int tid = threadIdx.x;
    int d = tid >> 2, p = tid & 3;
    const float* wr = Wv + ((size_t)h * 64 + d) * 1024;
    const float* vb = vbar + b * 1024;
    float s = 0.f;
    for (int kk = p * 4; kk < 1024; kk += 16) {
        float4 w4 = *(const float4*)(wr + kk);
        float4 v4 = *(const float4*)(vb + kk);
        s += w4.x * v4.x + w4.y * v4.y + w4.z * v4.z + w4.w * v4.w;
    }
    s += __shfl_xor_sync(0xffffffffu, s, 1);
    s += __shfl_xor_sync(0xffffffffu, s, 2);
    if (p == 0) vmean[bh * 64 + d] = s;
}

// ---------------------------------------------------------------------------
// Chunk-fused bf16 split GEMM, 4-deep half-chunk pipeline.
// CTA tile 128x256 (unchanged traffic); stage = 32 K-cols (A 16KB + W 32KB =
// 48KB), 4 buffers (192KB), prefetch distance 3 (wait_group 2).
// Stage row layout: [hi32 (64B) | lo32 (64B)], 8-quad XOR swizzle.
// mode 2 & z==0: acc scaled by 0.125 (folds 1/sqrt(DK) into Q).
// ---------------------------------------------------------------------------
#define STAGE_B 49152
#define GEMM_SMEM (4 * STAGE_B)     // 192KB

__device__ __forceinline__ void load_half(
    const __nv_bfloat16* __restrict__ Ap, const __nv_bfloat16* __restrict__ Wp,
    uint32_t base, int m0, int n0, int hc, int tid)
{
    int co = hc * 32;
#pragma unroll
    for (int i = 0; i < 4; i++) {       // A: 128 rows x 128B (hi32|lo32)
        int f = i * 256 + tid;
        int r = f >> 3, qd = f & 7;
        uint32_t sw = r * 128 + ((qd ^ (r & 7)) << 4);
        const void* g = Ap + (size_t)(m0 + r) * KROW + ((qd >> 2) << 10) + co + (qd & 3) * 8;
        asm volatile("cp.async.cg.shared.global [%0], [%1], 16;" :: "r"(base + sw), "l"(g));
    }
#pragma unroll
    for (int i = 0; i < 8; i++) {       // W: 256 rows x 128B (hi32|lo32)
        int f = i * 256 + tid;
        int r = f >> 3, qd = f & 7;
        uint32_t sw = r * 128 + ((qd ^ (r & 7)) << 4);
        const void* g = Wp + (size_t)(n0 + r) * KROW + ((qd >> 2) << 10) + co + (qd & 3) * 8;
        asm volatile("cp.async.cg.shared.global [%0], [%1], 16;" :: "r"(base + 16384 + sw), "l"(g));
    }
}

__global__ __launch_bounds__(256, 1)
void gemm_mma(const __nv_bfloat16* __restrict__ ApB, const __nv_bfloat16* __restrict__ WpB,
              void* C0, void* C1, void* C2, int mode)
{
    extern __shared__ __align__(128) char smem[];
    uint32_t sb = smem_u32(smem);
    int tid = threadIdx.x;
    int wid = tid >> 5, lane = tid & 31;
    int wm = wid >> 2, wn = wid & 3;
    int m0 = blockIdx.y * 128, n0 = blockIdx.x * 256;
    int z = blockIdx.z;
    const __nv_bfloat16* Ap = ApB + (size_t)z * ASEC;
    const __nv_bfloat16* Wp = WpB + (size_t)z * WSEC;
    void* Cv = (z == 0) ? C0 : (z == 1) ? C1 : C2;
    float scl = (mode == 2 && z == 0) ? 0.125f : 1.0f;

    float acc[4][8][4];
#pragma unroll
    for (int i = 0; i < 4; i++)
#pragma unroll
        for (int j = 0; j < 8; j++)
#pragma unroll
            for (int r = 0; r < 4; r++) acc[i][j][r] = 0.f;

    // prologue: half-chunks 0..2 into buffers 0..2
#pragma unroll
    for (int t = 0; t < 3; t++) {
        load_half(Ap, Wp, sb + t * STAGE_B, m0, n0, t, tid);
        asm volatile("cp.async.commit_group;" ::: "memory");
    }

    int lm15 = lane & 15, l4 = lane >> 4;

    for (int s = 0; s < NHC; s++) {
        asm volatile("cp.async.wait_group 2;" ::: "memory");
        __syncthreads();
        if (s + 3 < NHC)
            load_half(Ap, Wp, sb + ((s + 3) & 3) * STAGE_B, m0, n0, s + 3, tid);
        asm volatile("cp.async.commit_group;" ::: "memory");

        uint32_t B = sb + (s & 3) * STAGE_B;
        uint32_t AB = B, WB = B + 16384;

#pragma unroll
        for (int kk = 0; kk < 2; kk++) {
            int ch = 2 * kk + l4;           // hi quads 0..3
            int cl = 4 + 2 * kk + l4;       // lo quads 4..7
            uint32_t ah[4][4], al[4][4];
#pragma unroll
            for (int i = 0; i < 4; i++) {
                int r = wm * 64 + i * 16 + lm15;
                uint32_t rowb = AB + r * 128;
                asm volatile("ldmatrix.sync.aligned.m8n8.x4.shared.b16 {%0,%1,%2,%3}, [%4];"
                    : "=r"(ah[i][0]), "=r"(ah[i][1]), "=r"(ah[i][2]), "=r"(ah[i][3])
                    : "r"(rowb + ((ch ^ (r & 7)) << 4)));
                asm volatile("ldmatrix.sync.aligned.m8n8.x4.shared.b16 {%0,%1,%2,%3}, [%4];"
                    : "=r"(al[i][0]), "=r"(al[i][1]), "=r"(al[i][2]), "=r"(al[i][3])
                    : "r"(rowb + ((cl ^ (r & 7)) << 4)));
            }
#pragma unroll
            for (int g = 0; g < 4; g++) {
                int rW = wn * 64 + g * 16 + lm15;
                uint32_t rowb = WB + rW * 128;
                uint32_t bh4[4], bl4[4];
                asm volatile("ldmatrix.sync.aligned.m8n8.x4.shared.b16 {%0,%1,%2,%3}, [%4];"
                    : "=r"(bh4[0]), "=r"(bh4[1]), "=r"(bh4[2]), "=r"(bh4[3])
                    : "r"(rowb + ((ch ^ (rW & 7)) << 4)));
                asm volatile("ldmatrix.sync.aligned.m8n8.x4.shared.b16 {%0,%1,%2,%3}, [%4];"
                    : "=r"(bl4[0]), "=r"(bl4[1]), "=r"(bl4[2]), "=r"(bl4[3])
                    : "r"(rowb + ((cl ^ (rW & 7)) << 4)));
#pragma unroll
                for (int j2 = 0; j2 < 2; j2++) {
                    int j = g * 2 + j2;
                    uint32_t bh0 = bh4[j2], bh1 = bh4[j2 + 2];
                    uint32_t bl0 = bl4[j2], bl1 = bl4[j2 + 2];
#pragma unroll
                    for (int i = 0; i < 4; i++) {
                        asm volatile(
                            "mma.sync.aligned.m16n8k16.row.col.f32.bf16.bf16.f32 "
                            "{%0,%1,%2,%3}, {%4,%5,%6,%7}, {%8,%9}, {%0,%1,%2,%3};"
                            : "+f"(acc[i][j][0]), "+f"(acc[i][j][1]),
                              "+f"(acc[i][j][2]), "+f"(acc[i][j][3])
                            : "r"(ah[i][0]), "r"(ah[i][1]), "r"(ah[i][2]), "r"(ah[i][3]),
                              "r"(bh0), "r"(bh1));
                        asm volatile(
                            "mma.sync.aligned.m16n8k16.row.col.f32.bf16.bf16.f32 "
                            "{%0,%1,%2,%3}, {%4,%5,%6,%7}, {%8,%9}, {%0,%1,%2,%3};"
                            : "+f"(acc[i][j][0]), "+f"(acc[i][j][1]),
                              "+f"(acc[i][j][2]), "+f"(acc[i][j][3])
                            : "r"(al[i][0]), "r"(al[i][1]), "r"(al[i][2]), "r"(al[i][3]),
                              "r"(bh0), "r"(bh1));
                        asm volatile(
                            "mma.sync.aligned.m16n8k16.row.col.f32.bf16.bf16.f32 "
                            "{%0,%1,%2,%3}, {%4,%5,%6,%7}, {%8,%9}, {%0,%1,%2,%3};"
                            : "+f"(acc[i][j][0]), "+f"(acc[i][j][1]),
                              "+f"(acc[i][j][2]), "+f"(acc[i][j][3])
                            : "r"(ah[i][0]), "r"(ah[i][1]), "r"(ah[i][2]), "r"(ah[i][3]),
                              "r"(bl0), "r"(bl1));
                    }
                }
            }
        }
    }

    int lr = lane >> 2, lc = (lane & 3) * 2;
#pragma unroll
    for (int i = 0; i < 4; i++) {
#pragma unroll
        for (int j = 0; j < 8; j++) {
            int mA = m0 + wm * 64 + i * 16 + lr;
            int n  = n0 + wn * 64 + j * 8 + lc;
            if (mode == 0) {
                float* C = (float*)Cv;
                *(float2*)(C + (size_t)mA * 1024 + n) = make_float2(acc[i][j][0], acc[i][j][1]);
                *(float2*)(C + (size_t)(mA + 8) * 1024 + n) = make_float2(acc[i][j][2], acc[i][j][3]);
            } else {
                __nv_bfloat16* C = (__nv_bfloat16*)Cv;
                int hI = n >> 6, kk2 = n & 63;
                int bA = mA >> 10, sA = mA & 1023;
#pragma unroll
                for (int half = 0; half < 2; half++) {
                    float x0 = acc[i][j][half * 2] * scl, x1 = acc[i][j][half * 2 + 1] * scl;
                    __nv_bfloat16 h0 = __float2bfloat16(x0), h1 = __float2bfloat16(x1);
                    uint32_t hp = (uint32_t)__bfloat16_as_ushort(h0) |
                                  ((uint32_t)__bfloat16_as_ushort(h1) << 16);
                    uint32_t lq = pack_bf2(x0 - __bfloat162float(h0), x1 - __bfloat162float(h1));
                    size_t base = ((((size_t)bA * Hc + hI) << 10) + sA + half * 8) * 128 + kk2;
                    *(uint32_t*)(C + base)      = hp;
                    *(uint32_t*)(C + base + 64) = lq;
                }
            }
        }
    }
}

// ---------------------------------------------------------------------------
// FA2-style tensor-core attention (R13/R14 version: fullLive fast path,
// Q pre-scaled by 0.125 at projection).
// ---------------------------------------------------------------------------
#define ROWB 272
#define TILEB (128 * ROWB)
#define AT_SMEM (5 * TILEB)

__global__ __launch_bounds__(256, 1)
void attn_mma(const __nv_bfloat16* __restrict__ qs, const __nv_bfloat16* __restrict__ ks,
              const __nv_bfloat16* __restrict__ vs, const int* __restrict__ pm1,
              const int* __restrict__ pm2, const float* __restrict__ vmean,
              __nv_bfloat16* __restrict__ ap)
{
    extern __shared__ __align__(128) char smem[];
    uint32_t sb = smem_u32(smem);
    const uint32_t QS = sb;

    int tid = threadIdx.x, lane = tid & 31, w = tid >> 5;
    int lm15 = lane & 15, l4 = lane >> 4, lr = lane >> 2, lc = (lane & 3) * 2;
    int bh = blockIdx.y, b = bh >> 4, h = bh & 15;
    int i0 = blockIdx.x * 128;
    int p1 = pm1[b], p2 = pm2[b];

    int rw = w * 16;
    int gi0 = i0 + rw + lr, gi1 = gi0 + 8;
    bool fm0 = (gi0 >= p2) || (p1 == 0);
    bool fm1 = (gi1 >= p2) || (p1 == 0);

    int jt_max = 0;
    if (!((i0 >= p2) || (p1 == 0))) {
        int J = min(i0 + 128, p1);
        jt_max = (J + 127) >> 7;
    }

    float po[8][4];
#pragma unroll
    for (int nb = 0; nb < 8; nb++)
#pragma unroll
        for (int r = 0; r < 4; r++) po[nb][r] = 0.f;
    float ls0 = 0.f, ls1 = 0.f;

    if (jt_max > 0) {
        {
            const char* qg = (const char*)(qs + ((size_t)bh * 1024 + i0) * 128);
#pragma unroll
            for (int i = 0; i < 8; i++) {
                int f = i * 256 + tid; int r = f >> 4, c = f & 15;
                asm volatile("cp.async.cg.shared.global [%0], [%1], 16;"
                    :: "r"(QS + r * ROWB + c * 16), "l"(qg + r * 256 + c * 16));
            }
            asm volatile("cp.async.commit_group;" ::: "memory");
        }
        {
            const char* kg = (const char*)(ks + (size_t)bh * 1024 * 128);
            const char* vg = (const char*)(vs + (size_t)bh * 1024 * 128);
            uint32_t KB = sb + TILEB, VB = sb + 2 * TILEB;
#pragma unroll
            for (int i = 0; i < 8; i++) {
                int f = i * 256 + tid; int r = f >> 4, c = f & 15;
                asm volatile("cp.async.cg.shared.global [%0], [%1], 16;"
                    :: "r"(KB + r * ROWB + c * 16), "l"(kg + r * 256 + c * 16));
                asm volatile("cp.async.cg.shared.global [%0], [%1], 16;"
                    :: "r"(VB + r * ROWB + c * 16), "l"(vg + r * 256 + c * 16));
            }
            asm volatile("cp.async.commit_group;" ::: "memory");
        }

        for (int jt = 0; jt < jt_max; jt++) {
            int j0 = jt * 128;
            if (jt + 1 < jt_max) {
                int jn = (jt + 1) & 1;
                uint32_t KB = sb + (1 + 2 * jn) * TILEB;
                uint32_t VB = KB + TILEB;
                const char* kg = (const char*)(ks + ((size_t)bh * 1024 + (jt + 1) * 128) * 128);
                const char* vg = (const char*)(vs + ((size_t)bh * 1024 + (jt + 1) * 128) * 128);
#pragma unroll
                for (int i = 0; i < 8; i++) {
                    int f = i * 256 + tid; int r = f >> 4, c = f & 15;
                    asm volatile("cp.async.cg.shared.global [%0], [%1], 16;"
                        :: "r"(KB + r * ROWB + c * 16), "l"(kg + r * 256 + c * 16));
                    asm volatile("cp.async.cg.shared.global [%0], [%1], 16;"
                        :: "r"(VB + r * ROWB + c * 16), "l"(vg + r * 256 + c * 16));
                }
                asm volatile("cp.async.commit_group;" ::: "memory");
                asm volatile("cp.async.wait_group 1;" ::: "memory");
            } else {
                asm volatile("cp.async.wait_group 0;" ::: "memory");
            }
            __syncthreads();

            uint32_t KS = sb + (1 + 2 * (jt & 1)) * TILEB;
            uint32_t VS = KS + TILEB;

            float sc[16][4];
#pragma unroll
            for (int nb = 0; nb < 16; nb++)
#pragma unroll
                for (int r = 0; r < 4; r++) sc[nb][r] = 0.f;

#pragma unroll
            for (int ks4 = 0; ks4 < 4; ks4++) {
                uint32_t a_hi[4], a_lo[4], bb_h[8][4], bb_l[8][4];
                int ch = 2 * ks4 + l4, cl = 8 + 2 * ks4 + l4;
                asm volatile("ldmatrix.sync.aligned.m8n8.x4.shared.b16 {%0,%1,%2,%3}, [%4];"
                    : "=r"(a_hi[0]), "=r"(a_hi[1]), "=r"(a_hi[2]), "=r"(a_hi[3])
                    : "r"(QS + (rw + lm15) * ROWB + ch * 16));
                asm volatile("ldmatrix.sync.aligned.m8n8.x4.shared.b16 {%0,%1,%2,%3}, [%4];"
                    : "=r"(a_lo[0]), "=r"(a_lo[1]), "=r"(a_lo[2]), "=r"(a_lo[3])
                    : "r"(QS + (rw + lm15) * ROWB + cl * 16));
#pragma unroll
                for (int g = 0; g < 8; g++) {
                    asm volatile("ldmatrix.sync.aligned.m8n8.x4.shared.b16 {%0,%1,%2,%3}, [%4];"
                        : "=r"(bb_h[g][0]), "=r"(bb_h[g][1]), "=r"(bb_h[g][2]), "=r"(bb_h[g][3])
                        : "r"(KS + (g * 16 + lm15) * ROWB + ch * 16));
                    asm volatile("ldmatrix.sync.aligned.m8n8.x4.shared.b16 {%0,%1,%2,%3}, [%4];"
                        : "=r"(bb_l[g][0]), "=r"(bb_l[g][1]), "=r"(bb_l[g][2]), "=r"(bb_l[g][3])
                        : "r"(KS + (g * 16 + lm15) * ROWB + cl * 16));
                }
#pragma unroll
                for (int nb = 0; nb < 16; nb++) {
                    uint32_t bh0 = bb_h[nb >> 1][nb & 1], bh1 = bb_h[nb >> 1][(nb & 1) + 2];
                    uint32_t bl0 = bb_l[nb >> 1][nb & 1], bl1 = bb_l[nb >> 1][(nb & 1) + 2];
                    asm volatile(
                        "mma.sync.aligned.m16n8k16.row.col.f32.bf16.bf16.f32 "
                        "{%0,%1,%2,%3}, {%4,%5,%6,%7}, {%8,%9}, {%0,%1,%2,%3};"
                        : "+f"(sc[nb][0]), "+f"(sc[nb][1]), "+f"(sc[nb][2]), "+f"(sc[nb][3])
                        : "r"(a_hi[0]), "r"(a_hi[1]), "r"(a_hi[2]), "r"(a_hi[3]), "r"(bh0), "r"(bh1));
                    asm volatile(
                        "mma.sync.aligned.m16n8k16.row.col.f32.bf16.bf16.f32 "
                        "{%0,%1,%2,%3}, {%4,%5,%6,%7}, {%8,%9}, {%0,%1,%2,%3};"
                        : "+f"(sc[nb][0]), "+f"(sc[nb][1]), "+f"(sc[nb][2]), "+f"(sc[nb][3])
                        : "r"(a_hi[0]), "r"(a_hi[1]), "r"(a_hi[2]), "r"(a_hi[3]), "r"(bl0), "r"(bl1));
                    asm volatile(
                        "mma.sync.aligned.m16n8k16.row.col.f32.bf16.bf16.f32 "
                        "{%0,%1,%2,%3}, {%4,%5,%6,%7}, {%8,%9}, {%0,%1,%2,%3};"
                        : "+f"(sc[nb][0]), "+f"(sc[nb][1]), "+f"(sc[nb][2]), "+f"(sc[nb][3])
                        : "r"(a_lo[0]), "r"(a_lo[1]), "r"(a_lo[2]), "r"(a_lo[3]), "r"(bh0), "r"(bh1));
                }
            }

            bool fullLive = (jt < blockIdx.x) && (j0 + 128 <= p1);
            if (fullLive) {
#pragma unroll
                for (int nb = 0; nb < 16; nb++) {
                    float v00 = __expf(sc[nb][0]);
                    float v01 = __expf(sc[nb][1]);
                    float v10 = __expf(sc[nb][2]);
                    float v11 = __expf(sc[nb][3]);
                    ls0 += v00 + v01;
                    ls1 += v10 + v11;
                    sc[nb][0] = v00; sc[nb][1] = v01; sc[nb][2] = v10; sc[nb][3] = v11;
                }
            } else {
                int t0 = fm0 ? 0 : min(gi0 + 1, p1);
                int t1 = fm1 ? 0 : min(gi1 + 1, p1);
#pragma unroll
                for (int nb = 0; nb < 16; nb++) {
                    int gj0 = j0 + nb * 8 + lc, gj1 = gj0 + 1;
                    float v00 = (gj0 < t0) ? __expf(sc[nb][0]) : 0.f;
                    float v01 = (gj1 < t0) ? __expf(sc[nb][1]) : 0.f;
                    float v10 = (gj0 < t1) ? __expf(sc[nb][2]) : 0.f;
                    float v11 = (gj1 < t1) ? __expf(sc[nb][3]) : 0.f;
                    ls0 += v00 + v01;
                    ls1 += v10 + v11;
                    sc[nb][0] = v00; sc[nb][1] = v01; sc[nb][2] = v10; sc[nb][3] = v11;
                }
            }

#pragma unroll
            for (int t = 0; t < 8; t++) {
                uint32_t ahi[4], alo[4];
#pragma unroll
                for (int half = 0; half < 2; half++) {
                    float* s4 = sc[2 * t + half];
                    __nv_bfloat16 h0 = __float2bfloat16(s4[0]), h1 = __float2bfloat16(s4[1]);
                    __nv_bfloat16 h2 = __float2bfloat16(s4[2]), h3 = __float2bfloat16(s4[3]);
                    ahi[half * 2]     = (uint32_t)__bfloat16_as_ushort(h0) | ((uint32_t)__bfloat16_as_ushort(h1) << 16);
                    ahi[half * 2 + 1] = (uint32_t)__bfloat16_as_ushort(h2) | ((uint32_t)__bfloat16_as_ushort(h3) << 16);
                    alo[half * 2]     = pack_bf2(s4[0] - __bfloat162float(h0), s4[1] - __bfloat162float(h1));
                    alo[half * 2 + 1] = pack_bf2(s4[2] - __bfloat162float(h2), s4[3] - __bfloat162float(h3));
                }
                uint32_t af_hi[4] = { ahi[0], ahi[1], ahi[2], ahi[3] };
                uint32_t af_lo[4] = { alo[0], alo[1], alo[2], alo[3] };

                uint32_t bth[4][4], btl[4][4];
#pragma unroll
                for (int db = 0; db < 4; db++) {
                    int rv = t * 16 + lm15;
                    asm volatile("ldmatrix.sync.aligned.m8n8.x4.trans.shared.b16 {%0,%1,%2,%3}, [%4];"
                        : "=r"(bth[db][0]), "=r"(bth[db][1]), "=r"(bth[db][2]), "=r"(bth[db][3])
                        : "r"(VS + rv * ROWB + (db * 2 + l4) * 16));
                    asm volatile("ldmatrix.sync.aligned.m8n8.x4.trans.shared.b16 {%0,%1,%2,%3}, [%4];"
                        : "=r"(btl[db][0]), "=r"(btl[db][1]), "=r"(btl[db][2]), "=r"(btl[db][3])
                        : "r"(VS + rv * ROWB + (8 + db * 2 + l4) * 16));
                }
#pragma unroll
                for (int db = 0; db < 4; db++)
#pragma unroll
                    for (int nf = 0; nf < 2; nf++) {
                        int nb = db * 2 + nf;
                        asm volatile(
                            "mma.sync.aligned.m16n8k16.row.col.f32.bf16.bf16.f32 "
                            "{%0,%1,%2,%3}, {%4,%5,%6,%7}, {%8,%9}, {%0,%1,%2,%3};"
                            : "+f"(po[nb][0]), "+f"(po[nb][1]), "+f"(po[nb][2]), "+f"(po[nb][3])
                            : "r"(af_hi[0]), "r"(af_hi[1]), "r"(af_hi[2]), "r"(af_hi[3]),
                              "r"(bth[db][nf * 2]), "r"(bth[db][nf * 2 + 1]));
                        asm volatile(
                            "mma.sync.aligned.m16n8k16.row.col.f32.bf16.bf16.f32 "
                            "{%0,%1,%2,%3}, {%4,%5,%6,%7}, {%8,%9}, {%0,%1,%2,%3};"
                            : "+f"(po[nb][0]), "+f"(po[nb][1]), "+f"(po[nb][2]), "+f"(po[nb][3])
                            : "r"(af_hi[0]), "r"(af_hi[1]), "r"(af_hi[2]), "r"(af_hi[3]),
                              "r"(btl[db][nf * 2]), "r"(btl[db][nf * 2 + 1]));
                        asm volatile(
                            "mma.sync.aligned.m16n8k16.row.col.f32.bf16.bf16.f32 "
                            "{%0,%1,%2,%3}, {%4,%5,%6,%7}, {%8,%9}, {%0,%1,%2,%3};"
                            : "+f"(po[nb][0]), "+f"(po[nb][1]), "+f"(po[nb][2]), "+f"(po[nb][3])
                            : "r"(af_lo[0]), "r"(af_lo[1]), "r"(af_lo[2]), "r"(af_lo[3]),
                              "r"(bth[db][nf * 2]), "r"(bth[db][nf * 2 + 1]));
                    }
            }
            __syncthreads();
        }
    }

    ls0 += __shfl_xor_sync(0xffffffffu, ls0, 1);
    ls0 += __shfl_xor_sync(0xffffffffu, ls0, 2);
    ls1 += __shfl_xor_sync(0xffffffffu, ls1, 1);
    ls1 += __shfl_xor_sync(0xffffffffu, ls1, 2);
    float inv0 = fm0 ? 0.f : 1.0f / ls0;
    float inv1 = fm1 ? 0.f : 1.0f / ls1;

    size_t mr0 = ((size_t)b * 1024 + (i0 + rw + lr)) * (size_t)KROW;
    size_t mr1 = ((size_t)b * 1024 + (i0 + rw + lr + 8)) * (size_t)KROW;
#pragma unroll
    for (int nb = 0; nb < 8; nb++) {
        int d = nb * 8 + lc;
        int col = h * 64 + d;
        float x0, x1, y0, y1;
        if (fm0) { x0 = vmean[bh * 64 + d]; x1 = vmean[bh * 64 + d + 1]; }
        else     { x0 = po[nb][0] * inv0;   x1 = po[nb][1] * inv0; }
        if (fm1) { y0 = vmean[bh * 64 + d]; y1 = vmean[bh * 64 + d + 1]; }
        else     { y0 = po[nb][2] * inv1;   y1 = po[nb][3] * inv1; }

        __nv_bfloat16 hx0 = __float2bfloat16(x0), hx1 = __float2bfloat16(x1);
        uint32_t hp0 = (uint32_t)__bfloat16_as_ushort(hx0) | ((uint32_t)__bfloat16_as_ushort(hx1) << 16);
        uint32_t lq0 = pack_bf2(x0 - __bfloat162float(hx0), x1 - __bfloat162float(hx1));
        __nv_bfloat16 hy0 = __float2bfloat16(y0), hy1 = __float2bfloat16(y1);
        uint32_t hp1 = (uint32_t)__bfloat16_as_ushort(hy0) | ((uint32_t)__bfloat16_as_ushort(hy1) << 16);
        uint32_t lq1 = pack_bf2(y0 - __bfloat162float(hy0), y1 - __bfloat162float(hy1));

        *(uint32_t*)(ap + mr0 + col)        = hp0;
        *(uint32_t*)(ap + mr0 + col + 1024) = lq0;
        *(uint32_t*)(ap + mr1 + col)        = hp1;
        *(uint32_t*)(ap + mr1 + col + 1024) = lq1;
    }
}

// ---------------------------------------------------------------------------
extern "C" void kernel_launch(void* const* d_in, const int* in_sizes, int n_in,
                              void* d_out, int out_size)
{
    const float* q   = (const float*)d_in[0];
    const float* k   = (const float*)d_in[1];
    const float* v   = (const float*)d_in[2];
    const int*   pm1 = (const int*)d_in[3];
    const int*   pm2 = (const int*)d_in[4];
    const float* Wq  = (const float*)d_in[5];
    const float* Wk  = (const float*)d_in[6];
    const float* Wv  = (const float*)d_in[7];
    const float* Wo  = (const float*)d_in[8];
    float* out = (float*)d_out;

    __nv_bfloat16 *qs, *ksp, *vsp, *ap, *wp;
    float *vbar, *vmean;
    cudaGetSymbolAddress((void**)&qs,    g_qs);
    cudaGetSymbolAddress((void**)&ksp,   g_ks);
    cudaGetSymbolAddress((void**)&vsp,   g_vs);
    cudaGetSymbolAddress((void**)&ap,    g_ap);
    cudaGetSymbolAddress((void**)&wp,    g_wp);
    cudaGetSymbolAddress((void**)&vbar,  g_vbar);
    cudaGetSymbolAddress((void**)&vmean, g_vmean);

    cudaFuncSetAttribute(gemm_mma,
        cudaFuncAttributeMaxDynamicSharedMemorySize, GEMM_SMEM);
    cudaFuncSetAttribute(attn_mma,
        cudaFuncAttributeMaxDynamicSharedMemorySize, AT_SMEM);

    // vmean via linearity: full-chip parallel
    vbar_kernel<<<512, 256>>>(v, vbar);
    vmean_small<<<Bc * Hc, 256>>>(Wv, vbar, vmean);

    conv_w_all<<<dim3(512, 4), 256>>>(Wq, Wk, Wv, Wo, wp);
    conv_a3<<<dim3(4096, 3), 256>>>(q, k, v, ap);

    // Merged q/k/v projection GEMMs (Q output pre-scaled by 0.125)
    gemm_mma<<<dim3(Dc / 256, Mrows / 128, 3), 256, GEMM_SMEM>>>(
        ap, wp, (void*)qs, (void*)ksp, (void*)vsp, 2);

    attn_mma<<<dim3(Sc / 128, Bc * Hc), 256, AT_SMEM>>>(qs, ksp, vsp, pm1, pm2, vmean, ap);

    gemm_mma<<<dim3(Dc / 256, Mrows / 128, 1), 256, GEMM_SMEM>>>(
        ap, wp + 3 * WSEC, (void*)out, (void*)out, (void*)out, 0);
}

// round 16
// speedup vs baseline: 1.0716x; 1.0716x over previous
#include <cuda_runtime.h>
#include <cuda_bf16.h>
#include <math.h>
#include <stdint.h>

// Problem constants
#define Bc   8
#define Sc   1024
#define Dc   1024
#define Hc   16
#define Mrows (Bc*Sc)      // 8192
#define KROW 2048          // compact split: [hi(1024) | lo(1024)]
#define NCH  16            // 16 K-chunks of 64
#define ASEC ((size_t)Mrows*KROW)
#define WSEC ((size_t)Dc*KROW)

// ---------------- scratch (device globals: allocation-free) ----------------
__device__ __nv_bfloat16 g_qs[(size_t)Bc*Hc*Sc*128];
__device__ __nv_bfloat16 g_ks[(size_t)Bc*Hc*Sc*128];
__device__ __nv_bfloat16 g_vs[(size_t)Bc*Hc*Sc*128];
__device__ __nv_bfloat16 g_ap[3*ASEC];
__device__ __nv_bfloat16 g_wp[4*WSEC];
__device__ float g_vbar[Bc*1024];
__device__ float g_vmean[Bc*Hc*64];

__device__ __forceinline__ uint32_t smem_u32(const void* p) {
    uint32_t a;
    asm("{ .reg .u64 t; cvta.to.shared.u64 t, %1; cvt.u32.u64 %0, t; }"
        : "=r"(a) : "l"(p));
    return a;
}

__device__ __forceinline__ uint32_t pack_bf2(float a, float b) {
    __nv_bfloat16 ha = __float2bfloat16(a), hb = __float2bfloat16(b);
    return (uint32_t)__bfloat16_as_ushort(ha) | ((uint32_t)__bfloat16_as_ushort(hb) << 16);
}

// ---------------------------------------------------------------------------
// fp32 -> bf16 compact split conversions
// ---------------------------------------------------------------------------
__device__ __forceinline__ void conv8_core(const float* __restrict__ src,
                                           __nv_bfloat16* __restrict__ dst_hi,
                                           __nv_bfloat16* __restrict__ dst_lo)
{
    float4 x0 = *(const float4*)src;
    float4 x1 = *(const float4*)(src + 4);
    __nv_bfloat16 h0 = __float2bfloat16(x0.x), h1 = __float2bfloat16(x0.y);
    __nv_bfloat16 h2 = __float2bfloat16(x0.z), h3 = __float2bfloat16(x0.w);
    __nv_bfloat16 h4 = __float2bfloat16(x1.x), h5 = __float2bfloat16(x1.y);
    __nv_bfloat16 h6 = __float2bfloat16(x1.z), h7 = __float2bfloat16(x1.w);
    uint4 hv, lv;
    hv.x = (uint32_t)__bfloat16_as_ushort(h0) | ((uint32_t)__bfloat16_as_ushort(h1) << 16);
    hv.y = (uint32_t)__bfloat16_as_ushort(h2) | ((uint32_t)__bfloat16_as_ushort(h3) << 16);
    hv.z = (uint32_t)__bfloat16_as_ushort(h4) | ((uint32_t)__bfloat16_as_ushort(h5) << 16);
    hv.w = (uint32_t)__bfloat16_as_ushort(h6) | ((uint32_t)__bfloat16_as_ushort(h7) << 16);
    lv.x = pack_bf2(x0.x - __bfloat162float(h0), x0.y - __bfloat162float(h1));
    lv.y = pack_bf2(x0.z - __bfloat162float(h2), x0.w - __bfloat162float(h3));
    lv.z = pack_bf2(x1.x - __bfloat162float(h4), x1.y - __bfloat162float(h5));
    lv.w = pack_bf2(x1.z - __bfloat162float(h6), x1.w - __bfloat162float(h7));
    *(uint4*)dst_hi = hv;
    *(uint4*)dst_lo = lv;
}

__global__ __launch_bounds__(256) void conv_a3(
    const float* __restrict__ q, const float* __restrict__ k,
    const float* __restrict__ v, __nv_bfloat16* __restrict__ Y)
{
    const float* X = (blockIdx.y == 0) ? q : (blockIdx.y == 1) ? k : v;
    int i = blockIdx.x * 256 + threadIdx.x;
    int r = i >> 7;
    int c8 = (i & 127) << 3;
    size_t base = (size_t)blockIdx.y * ASEC + (size_t)r * KROW;
    conv8_core(X + (size_t)r * 1024 + c8, Y + base + c8, Y + base + 1024 + c8);
}

__global__ __launch_bounds__(256) void conv_w_all(
    const float* __restrict__ W0, const float* __restrict__ W1,
    const float* __restrict__ W2, const float* __restrict__ W3,
    __nv_bfloat16* __restrict__ Y)
{
    const float* X = (blockIdx.y == 0) ? W0 : (blockIdx.y == 1) ? W1
                   : (blockIdx.y == 2) ? W2 : W3;
    int i = blockIdx.x * 256 + threadIdx.x;
    int r = i >> 7;
    int c8 = (i & 127) << 3;
    size_t base = (size_t)blockIdx.y * WSEC + (size_t)r * KROW;
    conv8_core(X + (size_t)r * 1024 + c8, Y + base + c8, Y + base + 1024 + c8);
}

// ---------------------------------------------------------------------------
// vbar[b,k] = mean_s v[b,s,k]  — 512 CTAs (8 batches x 64 col-blocks of 16)
// ---------------------------------------------------------------------------
__global__ __launch_bounds__(256) void vbar_kernel(
    const float* __restrict__ v, float* __restrict__ vbar)
{
    __shared__ float sm[256];
    int b  = blockIdx.x >> 6;
    int cb = (blockIdx.x & 63) * 16;
    int tid = threadIdx.x;
    int col = tid & 15;
    int rg  = tid >> 4;
    const float* src = v + (size_t)b * 1024 * 1024 + cb;
    float s = 0.f;
    for (int r = rg; r < 1024; r += 16)
        s += src[(size_t)r * 1024 + col];
    sm[tid] = s;
    __syncthreads();
    if (rg < 8)  sm[tid] += sm[tid + 128];
    __syncthreads();
    if (rg < 4)  sm[tid] += sm[tid + 64];
    __syncthreads();
    if (rg < 2)  sm[tid] += sm[tid + 32];
    __syncthreads();
    if (rg == 0) {
        float r = sm[tid] + sm[tid + 16];
        vbar[b * 1024 + cb + col] = r * (1.0f / 1024.0f);
    }
}

__global__ __launch_bounds__(256) void vmean_small(
    const float* __restrict__ Wv, const float* __restrict__ vbar,
    float* __restrict__ vmean)
{
    int bh = blockIdx.x;
    int b = bh >> 4, h = bh & 15;
    int tid = threadIdx.x;
    int d = tid >> 2, p = tid & 3;
    const float* wr = Wv + ((size_t)h * 64 + d) * 1024;
    const float* vb = vbar + b * 1024;
    float s = 0.f;
    for (int kk = p * 4; kk < 1024; kk += 16) {
        float4 w4 = *(const float4*)(wr + kk);
        float4 v4 = *(const float4*)(vb + kk);
        s += w4.x * v4.x + w4.y * v4.y + w4.z * v4.z + w4.w * v4.w;
    }
    s += __shfl_xor_sync(0xffffffffu, s, 1);
    s += __shfl_xor_sync(0xffffffffu, s, 2);
    if (p == 0) vmean[bh * 64 + d] = s;
}

// ---------------------------------------------------------------------------
// Chunk-fused bf16 split GEMM (CTA 128x256, double-buffered 2x96KB).
// mode 2 & z==0 (Q projection): acc scaled by 0.125 (folds 1/sqrt(DK)).
// ---------------------------------------------------------------------------
#define STAGE_B 98304
#define GEMM_SMEM (2 * STAGE_B)

__device__ __forceinline__ void load_chunk(
    const __nv_bfloat16* __restrict__ Ap, const __nv_bfloat16* __restrict__ Wp,
    uint32_t base, int m0, int n0, int chunk, int tid)
{
    int co = chunk * 64;
#pragma unroll
    for (int i = 0; i < 4; i++) {
        int f = i * 256 + tid;
        int r = f >> 3, cx = f & 7;
        uint32_t sw = r * 128 + ((cx ^ (r & 7)) << 4);
        const void* gh = Ap + (size_t)(m0 + r) * KROW + co + cx * 8;
        asm volatile("cp.async.cg.shared.global [%0], [%1], 16;" :: "r"(base + sw), "l"(gh));
        const void* gl = Ap + (size_t)(m0 + r) * KROW + 1024 + co + cx * 8;
        asm volatile("cp.async.cg.shared.global [%0], [%1], 16;" :: "r"(base + 16384 + sw), "l"(gl));
    }
#pragma unroll
    for (int i = 0; i < 8; i++) {
        int f = i * 256 + tid;
        int r = f >> 3, cx = f & 7;
        uint32_t sw = r * 128 + ((cx ^ (r & 7)) << 4);
        const void* gh = Wp + (size_t)(n0 + r) * KROW + co + cx * 8;
        asm volatile("cp.async.cg.shared.global [%0], [%1], 16;" :: "r"(base + 32768 + sw), "l"(gh));
        const void* gl = Wp + (size_t)(n0 + r) * KROW + 1024 + co + cx * 8;
        asm volatile("cp.async.cg.shared.global [%0], [%1], 16;" :: "r"(base + 65536 + sw), "l"(gl));
    }
}

__global__ __launch_bounds__(256, 1)
void gemm_mma(const __nv_bfloat16* __restrict__ ApB, const __nv_bfloat16* __restrict__ WpB,
              void* C0, void* C1, void* C2, int mode)
{
    extern __shared__ __align__(128) char smem[];
    uint32_t sb = smem_u32(smem);
    int tid = threadIdx.x;
    int wid = tid >> 5, lane = tid & 31;
    int wm = wid >> 2, wn = wid & 3;
    int m0 = blockIdx.y * 128, n0 = blockIdx.x * 256;
    int z = blockIdx.z;
    const __nv_bfloat16* Ap = ApB + (size_t)z * ASEC;
    const __nv_bfloat16* Wp = WpB + (size_t)z * WSEC;
    void* Cv = (z == 0) ? C0 : (z == 1) ? C1 : C2;
    float scl = (mode == 2 && z == 0) ? 0.125f : 1.0f;   // fold 1/sqrt(DK) into Q

    float acc[4][8][4];
#pragma unroll
    for (int i = 0; i < 4; i++)
#pragma unroll
        for (int j = 0; j < 8; j++)
#pragma unroll
            for (int r = 0; r < 4; r++) acc[i][j][r] = 0.f;

    load_chunk(Ap, Wp, sb, m0, n0, 0, tid);
    asm volatile("cp.async.commit_group;" ::: "memory");

    int lm15 = lane & 15, l4 = lane >> 4;

    for (int s = 0; s < NCH; s++) {
        asm volatile("cp.async.wait_group 0;" ::: "memory");
        __syncthreads();
        if (s + 1 < NCH)
            load_chunk(Ap, Wp, sb + ((s + 1) & 1) * STAGE_B, m0, n0, s + 1, tid);
        asm volatile("cp.async.commit_group;" ::: "memory");

        uint32_t B = sb + (s & 1) * STAGE_B;
        uint32_t AH = B, AL = B + 16384, WH = B + 32768, WL = B + 65536;

#pragma unroll
        for (int kk = 0; kk < 4; kk++) {
            int c0 = 2 * kk + l4;
            uint32_t ah[4][4], al[4][4];
#pragma unroll
            for (int i = 0; i < 4; i++) {
                int r = wm * 64 + i * 16 + lm15;
                uint32_t sw = r * 128 + ((c0 ^ (r & 7)) << 4);
                asm volatile("ldmatrix.sync.aligned.m8n8.x4.shared.b16 {%0,%1,%2,%3}, [%4];"
                    : "=r"(ah[i][0]), "=r"(ah[i][1]), "=r"(ah[i][2]), "=r"(ah[i][3]) : "r"(AH + sw));
                asm volatile("ldmatrix.sync.aligned.m8n8.x4.shared.b16 {%0,%1,%2,%3}, [%4];"
                    : "=r"(al[i][0]), "=r"(al[i][1]), "=r"(al[i][2]), "=r"(al[i][3]) : "r"(AL + sw));
            }
#pragma unroll
            for (int g = 0; g < 4; g++) {
                int rW = wn * 64 + g * 16 + lm15;
                uint32_t swW = rW * 128 + ((c0 ^ (rW & 7)) << 4);
                uint32_t bh4[4], bl4[4];
                asm volatile("ldmatrix.sync.aligned.m8n8.x4.shared.b16 {%0,%1,%2,%3}, [%4];"
                    : "=r"(bh4[0]), "=r"(bh4[1]), "=r"(bh4[2]), "=r"(bh4[3]) : "r"(WH + swW));
                asm volatile("ldmatrix.sync.aligned.m8n8.x4.shared.b16 {%0,%1,%2,%3}, [%4];"
                    : "=r"(bl4[0]), "=r"(bl4[1]), "=r"(bl4[2]), "=r"(bl4[3]) : "r"(WL + swW));
#pragma unroll
                for (int j2 = 0; j2 < 2; j2++) {
                    int j = g * 2 + j2;
                    uint32_t bh0 = bh4[j2], bh1 = bh4[j2 + 2];
                    uint32_t bl0 = bl4[j2], bl1 = bl4[j2 + 2];
#pragma unroll
                    for (int i = 0; i < 4; i++) {
                        asm volatile(
                            "mma.sync.aligned.m16n8k16.row.col.f32.bf16.bf16.f32 "
                            "{%0,%1,%2,%3}, {%4,%5,%6,%7}, {%8,%9}, {%0,%1,%2,%3};"
                            : "+f"(acc[i][j][0]), "+f"(acc[i][j][1]),
                              "+f"(acc[i][j][2]), "+f"(acc[i][j][3])
                            : "r"(ah[i][0]), "r"(ah[i][1]), "r"(ah[i][2]), "r"(ah[i][3]),
                              "r"(bh0), "r"(bh1));
                        asm volatile(
                            "mma.sync.aligned.m16n8k16.row.col.f32.bf16.bf16.f32 "
                            "{%0,%1,%2,%3}, {%4,%5,%6,%7}, {%8,%9}, {%0,%1,%2,%3};"
                            : "+f"(acc[i][j][0]), "+f"(acc[i][j][1]),
                              "+f"(acc[i][j][2]), "+f"(acc[i][j][3])
                            : "r"(al[i][0]), "r"(al[i][1]), "r"(al[i][2]), "r"(al[i][3]),
                              "r"(bh0), "r"(bh1));
                        asm volatile(
                            "mma.sync.aligned.m16n8k16.row.col.f32.bf16.bf16.f32 "
                            "{%0,%1,%2,%3}, {%4,%5,%6,%7}, {%8,%9}, {%0,%1,%2,%3};"
                            : "+f"(acc[i][j][0]), "+f"(acc[i][j][1]),
                              "+f"(acc[i][j][2]), "+f"(acc[i][j][3])
                            : "r"(ah[i][0]), "r"(ah[i][1]), "r"(ah[i][2]), "r"(ah[i][3]),
                              "r"(bl0), "r"(bl1));
                    }
                }
            }
        }
    }

    int lr = lane >> 2, lc = (lane & 3) * 2;
#pragma unroll
    for (int i = 0; i < 4; i++) {
#pragma unroll
        for (int j = 0; j < 8; j++) {
            int mA = m0 + wm * 64 + i * 16 + lr;
            int n  = n0 + wn * 64 + j * 8 + lc;
            if (mode == 0) {
                float* C = (float*)Cv;
                *(float2*)(C + (size_t)mA * 1024 + n) = make_float2(acc[i][j][0], acc[i][j][1]);
                *(float2*)(C + (size_t)(mA + 8) * 1024 + n) = make_float2(acc[i][j][2], acc[i][j][3]);
            } else {
                __nv_bfloat16* C = (__nv_bfloat16*)Cv;
                int hI = n >> 6, kk2 = n & 63;
                int bA = mA >> 10, sA = mA & 1023;
#pragma unroll
                for (int half = 0; half < 2; half++) {
                    float x0 = acc[i][j][half * 2] * scl, x1 = acc[i][j][half * 2 + 1] * scl;
                    __nv_bfloat16 h0 = __float2bfloat16(x0), h1 = __float2bfloat16(x1);
                    uint32_t hp = (uint32_t)__bfloat16_as_ushort(h0) |
                                  ((uint32_t)__bfloat16_as_ushort(h1) << 16);
                    uint32_t lq = pack_bf2(x0 - __bfloat162float(h0), x1 - __bfloat162float(h1));
                    size_t base = ((((size_t)bA * Hc + hI) << 10) + sA + half * 8) * 128 + kk2;
                    *(uint32_t*)(C + base)      = hp;
                    *(uint32_t*)(C + base + 64) = lq;
                }
            }
        }
    }
}

// ---------------------------------------------------------------------------
// FA2-style tensor-core attention; fully-live tiles skip per-element masking.
// Q pre-scaled by 0.125 at projection.
// ---------------------------------------------------------------------------
#define ROWB 272
#define TILEB (128 * ROWB)
#define AT_SMEM (5 * TILEB)

__global__ __launch_bounds__(256, 1)
void attn_mma(const __nv_bfloat16* __restrict__ qs, const __nv_bfloat16* __restrict__ ks,
              const __nv_bfloat16* __restrict__ vs, const int* __restrict__ pm1,
              const int* __restrict__ pm2, const float* __restrict__ vmean,
              __nv_bfloat16* __restrict__ ap)
{
    extern __shared__ __align__(128) char smem[];
    uint32_t sb = smem_u32(smem);
    const uint32_t QS = sb;

    int tid = threadIdx.x, lane = tid & 31, w = tid >> 5;
    int lm15 = lane & 15, l4 = lane >> 4, lr = lane >> 2, lc = (lane & 3) * 2;
    int bh = blockIdx.y, b = bh >> 4, h = bh & 15;
    int i0 = blockIdx.x * 128;
    int p1 = pm1[b], p2 = pm2[b];

    int rw = w * 16;
    int gi0 = i0 + rw + lr, gi1 = gi0 + 8;
    bool fm0 = (gi0 >= p2) || (p1 == 0);
    bool fm1 = (gi1 >= p2) || (p1 == 0);

    int jt_max = 0;
    if (!((i0 >= p2) || (p1 == 0))) {
        int J = min(i0 + 128, p1);
        jt_max = (J + 127) >> 7;
    }

    float po[8][4];
#pragma unroll
    for (int nb = 0; nb < 8; nb++)
#pragma unroll
        for (int r = 0; r < 4; r++) po[nb][r] = 0.f;
    float ls0 = 0.f, ls1 = 0.f;

    if (jt_max > 0) {
        {
            const char* qg = (const char*)(qs + ((size_t)bh * 1024 + i0) * 128);
#pragma unroll
            for (int i = 0; i < 8; i++) {
                int f = i * 256 + tid; int r = f >> 4, c = f & 15;
                asm volatile("cp.async.cg.shared.global [%0], [%1], 16;"
                    :: "r"(QS + r * ROWB + c * 16), "l"(qg + r * 256 + c * 16));
            }
            asm volatile("cp.async.commit_group;" ::: "memory");
        }
        {
            const char* kg = (const char*)(ks + (size_t)bh * 1024 * 128);
            const char* vg = (const char*)(vs + (size_t)bh * 1024 * 128);
            uint32_t KB = sb + TILEB, VB = sb + 2 * TILEB;
#pragma unroll
            for (int i = 0; i < 8; i++) {
                int f = i * 256 + tid; int r = f >> 4, c = f & 15;
                asm volatile("cp.async.cg.shared.global [%0], [%1], 16;"
                    :: "r"(KB + r * ROWB + c * 16), "l"(kg + r * 256 + c * 16));
                asm volatile("cp.async.cg.shared.global [%0], [%1], 16;"
                    :: "r"(VB + r * ROWB + c * 16), "l"(vg + r * 256 + c * 16));
            }
            asm volatile("cp.async.commit_group;" ::: "memory");
        }

        for (int jt = 0; jt < jt_max; jt++) {
            int j0 = jt * 128;
            if (jt + 1 < jt_max) {
                int jn = (jt + 1) & 1;
                uint32_t KB = sb + (1 + 2 * jn) * TILEB;
                uint32_t VB = KB + TILEB;
                const char* kg = (const char*)(ks + ((size_t)bh * 1024 + (jt + 1) * 128) * 128);
                const char* vg = (const char*)(vs + ((size_t)bh * 1024 + (jt + 1) * 128) * 128);
#pragma unroll
                for (int i = 0; i < 8; i++) {
                    int f = i * 256 + tid; int r = f >> 4, c = f & 15;
                    asm volatile("cp.async.cg.shared.global [%0], [%1], 16;"
                        :: "r"(KB + r * ROWB + c * 16), "l"(kg + r * 256 + c * 16));
                    asm volatile("cp.async.cg.shared.global [%0], [%1], 16;"
                        :: "r"(VB + r * ROWB + c * 16), "l"(vg + r * 256 + c * 16));
                }
                asm volatile("cp.async.commit_group;" ::: "memory");
                asm volatile("cp.async.wait_group 1;" ::: "memory");
            } else {
                asm volatile("cp.async.wait_group 0;" ::: "memory");
            }
            __syncthreads();

            uint32_t KS = sb + (1 + 2 * (jt & 1)) * TILEB;
            uint32_t VS = KS + TILEB;

            float sc[16][4];
#pragma unroll
            for (int nb = 0; nb < 16; nb++)
#pragma unroll
                for (int r = 0; r < 4; r++) sc[nb][r] = 0.f;

#pragma unroll
            for (int ks4 = 0; ks4 < 4; ks4++) {
                uint32_t a_hi[4], a_lo[4], bb_h[8][4], bb_l[8][4];
                int ch = 2 * ks4 + l4, cl = 8 + 2 * ks4 + l4;
                asm volatile("ldmatrix.sync.aligned.m8n8.x4.shared.b16 {%0,%1,%2,%3}, [%4];"
                    : "=r"(a_hi[0]), "=r"(a_hi[1]), "=r"(a_hi[2]), "=r"(a_hi[3])
                    : "r"(QS + (rw + lm15) * ROWB + ch * 16));
                asm volatile("ldmatrix.sync.aligned.m8n8.x4.shared.b16 {%0,%1,%2,%3}, [%4];"
                    : "=r"(a_lo[0]), "=r"(a_lo[1]), "=r"(a_lo[2]), "=r"(a_lo[3])
                    : "r"(QS + (rw + lm15) * ROWB + cl * 16));
#pragma unroll
                for (int g = 0; g < 8; g++) {
                    asm volatile("ldmatrix.sync.aligned.m8n8.x4.shared.b16 {%0,%1,%2,%3}, [%4];"
                        : "=r"(bb_h[g][0]), "=r"(bb_h[g][1]), "=r"(bb_h[g][2]), "=r"(bb_h[g][3])
                        : "r"(KS + (g * 16 + lm15) * ROWB + ch * 16));
                    asm volatile("ldmatrix.sync.aligned.m8n8.x4.shared.b16 {%0,%1,%2,%3}, [%4];"
                        : "=r"(bb_l[g][0]), "=r"(bb_l[g][1]), "=r"(bb_l[g][2]), "=r"(bb_l[g][3])
                        : "r"(KS + (g * 16 + lm15) * ROWB + cl * 16));
                }
#pragma unroll
                for (int nb = 0; nb < 16; nb++) {
                    uint32_t bh0 = bb_h[nb >> 1][nb & 1], bh1 = bb_h[nb >> 1][(nb & 1) + 2];
                    uint32_t bl0 = bb_l[nb >> 1][nb & 1], bl1 = bb_l[nb >> 1][(nb & 1) + 2];
                    asm volatile(
                        "mma.sync.aligned.m16n8k16.row.col.f32.bf16.bf16.f32 "
                        "{%0,%1,%2,%3}, {%4,%5,%6,%7}, {%8,%9}, {%0,%1,%2,%3};"
                        : "+f"(sc[nb][0]), "+f"(sc[nb][1]), "+f"(sc[nb][2]), "+f"(sc[nb][3])
                        : "r"(a_hi[0]), "r"(a_hi[1]), "r"(a_hi[2]), "r"(a_hi[3]), "r"(bh0), "r"(bh1));
                    asm volatile(
                        "mma.sync.aligned.m16n8k16.row.col.f32.bf16.bf16.f32 "
                        "{%0,%1,%2,%3}, {%4,%5,%6,%7}, {%8,%9}, {%0,%1,%2,%3};"
                        : "+f"(sc[nb][0]), "+f"(sc[nb][1]), "+f"(sc[nb][2]), "+f"(sc[nb][3])
                        : "r"(a_hi[0]), "r"(a_hi[1]), "r"(a_hi[2]), "r"(a_hi[3]), "r"(bl0), "r"(bl1));
                    asm volatile(
                        "mma.sync.aligned.m16n8k16.row.col.f32.bf16.bf16.f32 "
                        "{%0,%1,%2,%3}, {%4,%5,%6,%7}, {%8,%9}, {%0,%1,%2,%3};"
                        : "+f"(sc[nb][0]), "+f"(sc[nb][1]), "+f"(sc[nb][2]), "+f"(sc[nb][3])
                        : "r"(a_lo[0]), "r"(a_lo[1]), "r"(a_lo[2]), "r"(a_lo[3]), "r"(bh0), "r"(bh1));
                }
            }

            bool fullLive = (jt < blockIdx.x) && (j0 + 128 <= p1);
            if (fullLive) {
#pragma unroll
                for (int nb = 0; nb < 16; nb++) {
                    float v00 = __expf(sc[nb][0]);
                    float v01 = __expf(sc[nb][1]);
                    float v10 = __expf(sc[nb][2]);
                    float v11 = __expf(sc[nb][3]);
                    ls0 += v00 + v01;
                    ls1 += v10 + v11;
                    sc[nb][0] = v00; sc[nb][1] = v01; sc[nb][2] = v10; sc[nb][3] = v11;
                }
            } else {
                int t0 = fm0 ? 0 : min(gi0 + 1, p1);
                int t1 = fm1 ? 0 : min(gi1 + 1, p1);
#pragma unroll
                for (int nb = 0; nb < 16; nb++) {
                    int gj0 = j0 + nb * 8 + lc, gj1 = gj0 + 1;
                    float v00 = (gj0 < t0) ? __expf(sc[nb][0]) : 0.f;
                    float v01 = (gj1 < t0) ? __expf(sc[nb][1]) : 0.f;
                    float v10 = (gj0 < t1) ? __expf(sc[nb][2]) : 0.f;
                    float v11 = (gj1 < t1) ? __expf(sc[nb][3]) : 0.f;
                    ls0 += v00 + v01;
                    ls1 += v10 + v11;
                    sc[nb][0] = v00; sc[nb][1] = v01; sc[nb][2] = v10; sc[nb][3] = v11;
                }
            }

#pragma unroll
            for (int t = 0; t < 8; t++) {
                uint32_t ahi[4], alo[4];
#pragma unroll
                for (int half = 0; half < 2; half++) {
                    float* s4 = sc[2 * t + half];
                    __nv_bfloat16 h0 = __float2bfloat16(s4[0]), h1 = __float2bfloat16(s4[1]);
                    __nv_bfloat16 h2 = __float2bfloat16(s4[2]), h3 = __float2bfloat16(s4[3]);
                    ahi[half * 2]     = (uint32_t)__bfloat16_as_ushort(h0) | ((uint32_t)__bfloat16_as_ushort(h1) << 16);
                    ahi[half * 2 + 1] = (uint32_t)__bfloat16_as_ushort(h2) | ((uint32_t)__bfloat16_as_ushort(h3) << 16);
                    alo[half * 2]     = pack_bf2(s4[0] - __bfloat162float(h0), s4[1] - __bfloat162float(h1));
                    alo[half * 2 + 1] = pack_bf2(s4[2] - __bfloat162float(h2), s4[3] - __bfloat162float(h3));
                }
                uint32_t af_hi[4] = { ahi[0], ahi[1], ahi[2], ahi[3] };
                uint32_t af_lo[4] = { alo[0], alo[1], alo[2], alo[3] };

                uint32_t bth[4][4], btl[4][4];
#pragma unroll
                for (int db = 0; db < 4; db++) {
                    int rv = t * 16 + lm15;
                    asm volatile("ldmatrix.sync.aligned.m8n8.x4.trans.shared.b16 {%0,%1,%2,%3}, [%4];"
                        : "=r"(bth[db][0]), "=r"(bth[db][1]), "=r"(bth[db][2]), "=r"(bth[db][3])
                        : "r"(VS + rv * ROWB + (db * 2 + l4) * 16));
                    asm volatile("ldmatrix.sync.aligned.m8n8.x4.trans.shared.b16 {%0,%1,%2,%3}, [%4];"
                        : "=r"(btl[db][0]), "=r"(btl[db][1]), "=r"(btl[db][2]), "=r"(btl[db][3])
                        : "r"(VS + rv * ROWB + (8 + db * 2 + l4) * 16));
                }
#pragma unroll
                for (int db = 0; db < 4; db++)
#pragma unroll
                    for (int nf = 0; nf < 2; nf++) {
                        int nb = db * 2 + nf;
                        asm volatile(
                            "mma.sync.aligned.m16n8k16.row.col.f32.bf16.bf16.f32 "
                            "{%0,%1,%2,%3}, {%4,%5,%6,%7}, {%8,%9}, {%0,%1,%2,%3};"
                            : "+f"(po[nb][0]), "+f"(po[nb][1]), "+f"(po[nb][2]), "+f"(po[nb][3])
                            : "r"(af_hi[0]), "r"(af_hi[1]), "r"(af_hi[2]), "r"(af_hi[3]),
                              "r"(bth[db][nf * 2]), "r"(bth[db][nf * 2 + 1]));
                        asm volatile(
                            "mma.sync.aligned.m16n8k16.row.col.f32.bf16.bf16.f32 "
                            "{%0,%1,%2,%3}, {%4,%5,%6,%7}, {%8,%9}, {%0,%1,%2,%3};"
                            : "+f"(po[nb][0]), "+f"(po[nb][1]), "+f"(po[nb][2]), "+f"(po[nb][3])
                            : "r"(af_hi[0]), "r"(af_hi[1]), "r"(af_hi[2]), "r"(af_hi[3]),
                              "r"(btl[db][nf * 2]), "r"(btl[db][nf * 2 + 1]));
                        asm volatile(
                            "mma.sync.aligned.m16n8k16.row.col.f32.bf16.bf16.f32 "
                            "{%0,%1,%2,%3}, {%4,%5,%6,%7}, {%8,%9}, {%0,%1,%2,%3};"
                            : "+f"(po[nb][0]), "+f"(po[nb][1]), "+f"(po[nb][2]), "+f"(po[nb][3])
                            : "r"(af_lo[0]), "r"(af_lo[1]), "r"(af_lo[2]), "r"(af_lo[3]),
                              "r"(bth[db][nf * 2]), "r"(bth[db][nf * 2 + 1]));
                    }
            }
            __syncthreads();
        }
    }

    ls0 += __shfl_xor_sync(0xffffffffu, ls0, 1);
    ls0 += __shfl_xor_sync(0xffffffffu, ls0, 2);
    ls1 += __shfl_xor_sync(0xffffffffu, ls1, 1);
    ls1 += __shfl_xor_sync(0xffffffffu, ls1, 2);
    float inv0 = fm0 ? 0.f : 1.0f / ls0;
    float inv1 = fm1 ? 0.f : 1.0f / ls1;

    size_t mr0 = ((size_t)b * 1024 + (i0 + rw + lr)) * (size_t)KROW;
    size_t mr1 = ((size_t)b * 1024 + (i0 + rw + lr + 8)) * (size_t)KROW;
#pragma unroll
    for (int nb = 0; nb < 8; nb++) {
        int d = nb * 8 + lc;
        int col = h * 64 + d;
        float x0, x1, y0, y1;
        if (fm0) { x0 = vmean[bh * 64 + d]; x1 = vmean[bh * 64 + d + 1]; }
        else     { x0 = po[nb][0] * inv0;   x1 = po[nb][1] * inv0; }
        if (fm1) { y0 = vmean[bh * 64 + d]; y1 = vmean[bh * 64 + d + 1]; }
        else     { y0 = po[nb][2] * inv1;   y1 = po[nb][3] * inv1; }

        __nv_bfloat16 hx0 = __float2bfloat16(x0), hx1 = __float2bfloat16(x1);
        uint32_t hp0 = (uint32_t)__bfloat16_as_ushort(hx0) | ((uint32_t)__bfloat16_as_ushort(hx1) << 16);
        uint32_t lq0 = pack_bf2(x0 - __bfloat162float(hx0), x1 - __bfloat162float(hx1));
        __nv_bfloat16 hy0 = __float2bfloat16(y0), hy1 = __float2bfloat16(y1);
        uint32_t hp1 = (uint32_t)__bfloat16_as_ushort(hy0) | ((uint32_t)__bfloat16_as_ushort(hy1) << 16);
        uint32_t lq1 = pack_bf2(y0 - __bfloat162float(hy0), y1 - __bfloat162float(hy1));

        *(uint32_t*)(ap + mr0 + col)        = hp0;
        *(uint32_t*)(ap + mr0 + col + 1024) = lq0;
        *(uint32_t*)(ap + mr1 + col)        = hp1;
        *(uint32_t*)(ap + mr1 + col + 1024) = lq1;
    }
}

// ---------------------------------------------------------------------------
extern "C" void kernel_launch(void* const* d_in, const int* in_sizes, int n_in,
                              void* d_out, int out_size)
{
    const float* q   = (const float*)d_in[0];
    const float* k   = (const float*)d_in[1];
    const float* v   = (const float*)d_in[2];
    const int*   pm1 = (const int*)d_in[3];
    const int*   pm2 = (const int*)d_in[4];
    const float* Wq  = (const float*)d_in[5];
    const float* Wk  = (const float*)d_in[6];
    const float* Wv  = (const float*)d_in[7];
    const float* Wo  = (const float*)d_in[8];
    float* out = (float*)d_out;

    __nv_bfloat16 *qs, *ksp, *vsp, *ap, *wp;
    float *vbar, *vmean;
    cudaGetSymbolAddress((void**)&qs,    g_qs);
    cudaGetSymbolAddress((void**)&ksp,   g_ks);
    cudaGetSymbolAddress((void**)&vsp,   g_vs);
    cudaGetSymbolAddress((void**)&ap,    g_ap);
    cudaGetSymbolAddress((void**)&wp,    g_wp);
    cudaGetSymbolAddress((void**)&vbar,  g_vbar);
    cudaGetSymbolAddress((void**)&vmean, g_vmean);

    cudaFuncSetAttribute(gemm_mma,
        cudaFuncAttributeMaxDynamicSharedMemorySize, GEMM_SMEM);
    cudaFuncSetAttribute(attn_mma,
        cudaFuncAttributeMaxDynamicSharedMemorySize, AT_SMEM);

    // vmean via linearity: full-chip parallel
    vbar_kernel<<<512, 256>>>(v, vbar);
    vmean_small<<<Bc * Hc, 256>>>(Wv, vbar, vmean);

    conv_w_all<<<dim3(512, 4), 256>>>(Wq, Wk, Wv, Wo, wp);
    conv_a3<<<dim3(4096, 3), 256>>>(q, k, v, ap);

    // Merged q/k/v projection GEMMs (Q output pre-scaled by 0.125)
    gemm_mma<<<dim3(Dc / 256, Mrows / 128, 3), 256, GEMM_SMEM>>>(
        ap, wp, (void*)qs, (void*)ksp, (void*)vsp, 2);

    attn_mma<<<dim3(Sc / 128, Bc * Hc), 256, AT_SMEM>>>(qs, ksp, vsp, pm1, pm2, vmean, ap);

    gemm_mma<<<dim3(Dc / 256, Mrows / 128, 1), 256, GEMM_SMEM>>>(
        ap, wp + 3 * WSEC, (void*)out, (void*)out, (void*)out, 0);
}

// round 17
// speedup vs baseline: 1.0765x; 1.0045x over previous
#include <cuda_runtime.h>
#include <cuda_bf16.h>
#include <math.h>
#include <stdint.h>

// Problem constants
#define Bc   8
#define Sc   1024
#define Dc   1024
#define Hc   16
#define Mrows (Bc*Sc)      // 8192
#define KROW 2048          // compact split: [hi(1024) | lo(1024)]
#define NCH  16            // 16 K-chunks of 64
#define ASEC ((size_t)Mrows*KROW)
#define WSEC ((size_t)Dc*KROW)

// ---------------- scratch (device globals: allocation-free) ----------------
__device__ __nv_bfloat16 g_qs[(size_t)Bc*Hc*Sc*128];
__device__ __nv_bfloat16 g_ks[(size_t)Bc*Hc*Sc*128];
__device__ __nv_bfloat16 g_vs[(size_t)Bc*Hc*Sc*128];
__device__ __nv_bfloat16 g_ap[3*ASEC];
__device__ __nv_bfloat16 g_wp[4*WSEC];
__device__ float g_vbar[Bc*1024];
__device__ float g_vmean[Bc*Hc*64];

__device__ __forceinline__ uint32_t smem_u32(const void* p) {
    uint32_t a;
    asm("{ .reg .u64 t; cvta.to.shared.u64 t, %1; cvt.u32.u64 %0, t; }"
        : "=r"(a) : "l"(p));
    return a;
}

__device__ __forceinline__ uint32_t pack_bf2(float a, float b) {
    __nv_bfloat16 ha = __float2bfloat16(a), hb = __float2bfloat16(b);
    return (uint32_t)__bfloat16_as_ushort(ha) | ((uint32_t)__bfloat16_as_ushort(hb) << 16);
}

// ---------------------------------------------------------------------------
// fp32 -> bf16 compact split core
// ---------------------------------------------------------------------------
__device__ __forceinline__ void conv8_core(const float* __restrict__ src,
                                           __nv_bfloat16* __restrict__ dst_hi,
                                           __nv_bfloat16* __restrict__ dst_lo)
{
    float4 x0 = *(const float4*)src;
    float4 x1 = *(const float4*)(src + 4);
    __nv_bfloat16 h0 = __float2bfloat16(x0.x), h1 = __float2bfloat16(x0.y);
    __nv_bfloat16 h2 = __float2bfloat16(x0.z), h3 = __float2bfloat16(x0.w);
    __nv_bfloat16 h4 = __float2bfloat16(x1.x), h5 = __float2bfloat16(x1.y);
    __nv_bfloat16 h6 = __float2bfloat16(x1.z), h7 = __float2bfloat16(x1.w);
    uint4 hv, lv;
    hv.x = (uint32_t)__bfloat16_as_ushort(h0) | ((uint32_t)__bfloat16_as_ushort(h1) << 16);
    hv.y = (uint32_t)__bfloat16_as_ushort(h2) | ((uint32_t)__bfloat16_as_ushort(h3) << 16);
    hv.z = (uint32_t)__bfloat16_as_ushort(h4) | ((uint32_t)__bfloat16_as_ushort(h5) << 16);
    hv.w = (uint32_t)__bfloat16_as_ushort(h6) | ((uint32_t)__bfloat16_as_ushort(h7) << 16);
    lv.x = pack_bf2(x0.x - __bfloat162float(h0), x0.y - __bfloat162float(h1));
    lv.y = pack_bf2(x0.z - __bfloat162float(h2), x0.w - __bfloat162float(h3));
    lv.z = pack_bf2(x1.x - __bfloat162float(h4), x1.y - __bfloat162float(h5));
    lv.w = pack_bf2(x1.z - __bfloat162float(h6), x1.w - __bfloat162float(h7));
    *(uint4*)dst_hi = hv;
    *(uint4*)dst_lo = lv;
}

// ---------------------------------------------------------------------------
// Mega pre-pipeline kernel: one launch covers
//   blocks [0,512):      vbar (8 batches x 64 col-blocks of 16)
//   blocks [512,2560):   W splits (4 matrices x 512 blocks)
//   blocks [2560,14848): A splits (q,k,v x 4096 blocks)
// ---------------------------------------------------------------------------
__global__ __launch_bounds__(256) void conv_mega(
    const float* __restrict__ q, const float* __restrict__ k,
    const float* __restrict__ v,
    const float* __restrict__ W0, const float* __restrict__ W1,
    const float* __restrict__ W2, const float* __restrict__ W3,
    __nv_bfloat16* __restrict__ Ya, __nv_bfloat16* __restrict__ Yw,
    float* __restrict__ vbar)
{
    __shared__ float sm[256];
    int blk = blockIdx.x;
    int tid = threadIdx.x;

    if (blk < 512) {
        // ---- vbar[b,k] = mean_s v[b,s,k] ----
        int b  = blk >> 6;
        int cb = (blk & 63) * 16;
        int col = tid & 15;
        int rg  = tid >> 4;
        const float* src = v + (size_t)b * 1024 * 1024 + cb;
        float s = 0.f;
        for (int r = rg; r < 1024; r += 16)
            s += src[(size_t)r * 1024 + col];
        sm[tid] = s;
        __syncthreads();
        if (rg < 8)  sm[tid] += sm[tid + 128];
        __syncthreads();
        if (rg < 4)  sm[tid] += sm[tid + 64];
        __syncthreads();
        if (rg < 2)  sm[tid] += sm[tid + 32];
        __syncthreads();
        if (rg == 0) {
            float r = sm[tid] + sm[tid + 16];
            vbar[b * 1024 + cb + col] = r * (1.0f / 1024.0f);
        }
        return;
    }
    blk -= 512;
    if (blk < 2048) {
        // ---- W splits ----
        int w = blk >> 9;
        const float* X = (w == 0) ? W0 : (w == 1) ? W1 : (w == 2) ? W2 : W3;
        int i = (blk & 511) * 256 + tid;
        int r = i >> 7;
        int c8 = (i & 127) << 3;
        size_t base = (size_t)w * WSEC + (size_t)r * KROW;
        conv8_core(X + (size_t)r * 1024 + c8, Yw + base + c8, Yw + base + 1024 + c8);
        return;
    }
    blk -= 2048;
    // ---- A splits (q,k,v) ----
    int y = blk >> 12;
    const float* X = (y == 0) ? q : (y == 1) ? k : v;
    int i = (blk & 4095) * 256 + tid;
    int r = i >> 7;
    int c8 = (i & 127) << 3;
    size_t base = (size_t)y * ASEC + (size_t)r * KROW;
    conv8_core(X + (size_t)r * 1024 + c8, Ya + base + c8, Ya + base + 1024 + c8);
}

// vmean[b,h*64+d] = dot(Wv[(h*64+d), :], vbar[b,:])
__global__ __launch_bounds__(256) void vmean_small(
    const float* __restrict__ Wv, const float* __restrict__ vbar,
    float* __restrict__ vmean)
{
    int bh = blockIdx.x;
    int b = bh >> 4, h = bh & 15;
    int tid = threadIdx.x;
    int d = tid >> 2, p = tid & 3;
    const float* wr = Wv + ((size_t)h * 64 + d) * 1024;
    const float* vb = vbar + b * 1024;
    float s = 0.f;
    for (int kk = p * 4; kk < 1024; kk += 16) {
        float4 w4 = *(const float4*)(wr + kk);
        float4 v4 = *(const float4*)(vb + kk);
        s += w4.x * v4.x + w4.y * v4.y + w4.z * v4.z + w4.w * v4.w;
    }
    s += __shfl_xor_sync(0xffffffffu, s, 1);
    s += __shfl_xor_sync(0xffffffffu, s, 2);
    if (p == 0) vmean[bh * 64 + d] = s;
}

// ---------------------------------------------------------------------------
// Chunk-fused bf16 split GEMM (CTA 128x256, double-buffered 2x96KB).
// mode 2 & z==0 (Q projection): acc scaled by 0.125 (folds 1/sqrt(DK)).
// ---------------------------------------------------------------------------
#define STAGE_B 98304
#define GEMM_SMEM (2 * STAGE_B)

__device__ __forceinline__ void load_chunk(
    const __nv_bfloat16* __restrict__ Ap, const __nv_bfloat16* __restrict__ Wp,
    uint32_t base, int m0, int n0, int chunk, int tid)
{
    int co = chunk * 64;
#pragma unroll
    for (int i = 0; i < 4; i++) {
        int f = i * 256 + tid;
        int r = f >> 3, cx = f & 7;
        uint32_t sw = r * 128 + ((cx ^ (r & 7)) << 4);
        const void* gh = Ap + (size_t)(m0 + r) * KROW + co + cx * 8;
        asm volatile("cp.async.cg.shared.global [%0], [%1], 16;" :: "r"(base + sw), "l"(gh));
        const void* gl = Ap + (size_t)(m0 + r) * KROW + 1024 + co + cx * 8;
        asm volatile("cp.async.cg.shared.global [%0], [%1], 16;" :: "r"(base + 16384 + sw), "l"(gl));
    }
#pragma unroll
    for (int i = 0; i < 8; i++) {
        int f = i * 256 + tid;
        int r = f >> 3, cx = f & 7;
        uint32_t sw = r * 128 + ((cx ^ (r & 7)) << 4);
        const void* gh = Wp + (size_t)(n0 + r) * KROW + co + cx * 8;
        asm volatile("cp.async.cg.shared.global [%0], [%1], 16;" :: "r"(base + 32768 + sw), "l"(gh));
        const void* gl = Wp + (size_t)(n0 + r) * KROW + 1024 + co + cx * 8;
        asm volatile("cp.async.cg.shared.global [%0], [%1], 16;" :: "r"(base + 65536 + sw), "l"(gl));
    }
}

__global__ __launch_bounds__(256, 1)
void gemm_mma(const __nv_bfloat16* __restrict__ ApB, const __nv_bfloat16* __restrict__ WpB,
              void* C0, void* C1, void* C2, int mode)
{
    extern __shared__ __align__(128) char smem[];
    uint32_t sb = smem_u32(smem);
    int tid = threadIdx.x;
    int wid = tid >> 5, lane = tid & 31;
    int wm = wid >> 2, wn = wid & 3;
    int m0 = blockIdx.y * 128, n0 = blockIdx.x * 256;
    int z = blockIdx.z;
    const __nv_bfloat16* Ap = ApB + (size_t)z * ASEC;
    const __nv_bfloat16* Wp = WpB + (size_t)z * WSEC;
    void* Cv = (z == 0) ? C0 : (z == 1) ? C1 : C2;
    float scl = (mode == 2 && z == 0) ? 0.125f : 1.0f;   // fold 1/sqrt(DK) into Q

    float acc[4][8][4];
#pragma unroll
    for (int i = 0; i < 4; i++)
#pragma unroll
        for (int j = 0; j < 8; j++)
#pragma unroll
            for (int r = 0; r < 4; r++) acc[i][j][r] = 0.f;

    load_chunk(Ap, Wp, sb, m0, n0, 0, tid);
    asm volatile("cp.async.commit_group;" ::: "memory");

    int lm15 = lane & 15, l4 = lane >> 4;

    for (int s = 0; s < NCH; s++) {
        asm volatile("cp.async.wait_group 0;" ::: "memory");
        __syncthreads();
        if (s + 1 < NCH)
            load_chunk(Ap, Wp, sb + ((s + 1) & 1) * STAGE_B, m0, n0, s + 1, tid);
        asm volatile("cp.async.commit_group;" ::: "memory");

        uint32_t B = sb + (s & 1) * STAGE_B;
        uint32_t AH = B, AL = B + 16384, WH = B + 32768, WL = B + 65536;

#pragma unroll
        for (int kk = 0; kk < 4; kk++) {
            int c0 = 2 * kk + l4;
            uint32_t ah[4][4], al[4][4];
#pragma unroll
            for (int i = 0; i < 4; i++) {
                int r = wm * 64 + i * 16 + lm15;
                uint32_t sw = r * 128 + ((c0 ^ (r & 7)) << 4);
                asm volatile("ldmatrix.sync.aligned.m8n8.x4.shared.b16 {%0,%1,%2,%3}, [%4];"
                    : "=r"(ah[i][0]), "=r"(ah[i][1]), "=r"(ah[i][2]), "=r"(ah[i][3]) : "r"(AH + sw));
                asm volatile("ldmatrix.sync.aligned.m8n8.x4.shared.b16 {%0,%1,%2,%3}, [%4];"
                    : "=r"(al[i][0]), "=r"(al[i][1]), "=r"(al[i][2]), "=r"(al[i][3]) : "r"(AL + sw));
            }
#pragma unroll
            for (int g = 0; g < 4; g++) {
                int rW = wn * 64 + g * 16 + lm15;
                uint32_t swW = rW * 128 + ((c0 ^ (rW & 7)) << 4);
                uint32_t bh4[4], bl4[4];
                asm volatile("ldmatrix.sync.aligned.m8n8.x4.shared.b16 {%0,%1,%2,%3}, [%4];"
                    : "=r"(bh4[0]), "=r"(bh4[1]), "=r"(bh4[2]), "=r"(bh4[3]) : "r"(WH + swW));
                asm volatile("ldmatrix.sync.aligned.m8n8.x4.shared.b16 {%0,%1,%2,%3}, [%4];"
                    : "=r"(bl4[0]), "=r"(bl4[1]), "=r"(bl4[2]), "=r"(bl4[3]) : "r"(WL + swW));
#pragma unroll
                for (int j2 = 0; j2 < 2; j2++) {
                    int j = g * 2 + j2;
                    uint32_t bh0 = bh4[j2], bh1 = bh4[j2 + 2];
                    uint32_t bl0 = bl4[j2], bl1 = bl4[j2 + 2];
#pragma unroll
                    for (int i = 0; i < 4; i++) {
                        asm volatile(
                            "mma.sync.aligned.m16n8k16.row.col.f32.bf16.bf16.f32 "
                            "{%0,%1,%2,%3}, {%4,%5,%6,%7}, {%8,%9}, {%0,%1,%2,%3};"
                            : "+f"(acc[i][j][0]), "+f"(acc[i][j][1]),
                              "+f"(acc[i][j][2]), "+f"(acc[i][j][3])
                            : "r"(ah[i][0]), "r"(ah[i][1]), "r"(ah[i][2]), "r"(ah[i][3]),
                              "r"(bh0), "r"(bh1));
                        asm volatile(
                            "mma.sync.aligned.m16n8k16.row.col.f32.bf16.bf16.f32 "
                            "{%0,%1,%2,%3}, {%4,%5,%6,%7}, {%8,%9}, {%0,%1,%2,%3};"
                            : "+f"(acc[i][j][0]), "+f"(acc[i][j][1]),
                              "+f"(acc[i][j][2]), "+f"(acc[i][j][3])
                            : "r"(al[i][0]), "r"(al[i][1]), "r"(al[i][2]), "r"(al[i][3]),
                              "r"(bh0), "r"(bh1));
                        asm volatile(
                            "mma.sync.aligned.m16n8k16.row.col.f32.bf16.bf16.f32 "
                            "{%0,%1,%2,%3}, {%4,%5,%6,%7}, {%8,%9}, {%0,%1,%2,%3};"
                            : "+f"(acc[i][j][0]), "+f"(acc[i][j][1]),
                              "+f"(acc[i][j][2]), "+f"(acc[i][j][3])
                            : "r"(ah[i][0]), "r"(ah[i][1]), "r"(ah[i][2]), "r"(ah[i][3]),
                              "r"(bl0), "r"(bl1));
                    }
                }
            }
        }
    }

    int lr = lane >> 2, lc = (lane & 3) * 2;
#pragma unroll
    for (int i = 0; i < 4; i++) {
#pragma unroll
        for (int j = 0; j < 8; j++) {
            int mA = m0 + wm * 64 + i * 16 + lr;
            int n  = n0 + wn * 64 + j * 8 + lc;
            if (mode == 0) {
                float* C = (float*)Cv;
                *(float2*)(C + (size_t)mA * 1024 + n) = make_float2(acc[i][j][0], acc[i][j][1]);
                *(float2*)(C + (size_t)(mA + 8) * 1024 + n) = make_float2(acc[i][j][2], acc[i][j][3]);
            } else {
                __nv_bfloat16* C = (__nv_bfloat16*)Cv;
                int hI = n >> 6, kk2 = n & 63;
                int bA = mA >> 10, sA = mA & 1023;
#pragma unroll
                for (int half = 0; half < 2; half++) {
                    float x0 = acc[i][j][half * 2] * scl, x1 = acc[i][j][half * 2 + 1] * scl;
                    __nv_bfloat16 h0 = __float2bfloat16(x0), h1 = __float2bfloat16(x1);
                    uint32_t hp = (uint32_t)__bfloat16_as_ushort(h0) |
                                  ((uint32_t)__bfloat16_as_ushort(h1) << 16);
                    uint32_t lq = pack_bf2(x0 - __bfloat162float(h0), x1 - __bfloat162float(h1));
                    size_t base = ((((size_t)bA * Hc + hI) << 10) + sA + half * 8) * 128 + kk2;
                    *(uint32_t*)(C + base)      = hp;
                    *(uint32_t*)(C + base + 64) = lq;
                }
            }
        }
    }
}

// ---------------------------------------------------------------------------
// FA2-style tensor-core attention; fully-live tiles skip per-element masking.
// Q pre-scaled by 0.125 at projection.
// ---------------------------------------------------------------------------
#define ROWB 272
#define TILEB (128 * ROWB)
#define AT_SMEM (5 * TILEB)

__global__ __launch_bounds__(256, 1)
void attn_mma(const __nv_bfloat16* __restrict__ qs, const __nv_bfloat16* __restrict__ ks,
              const __nv_bfloat16* __restrict__ vs, const int* __restrict__ pm1,
              const int* __restrict__ pm2, const float* __restrict__ vmean,
              __nv_bfloat16* __restrict__ ap)
{
    extern __shared__ __align__(128) char smem[];
    uint32_t sb = smem_u32(smem);
    const uint32_t QS = sb;

    int tid = threadIdx.x, lane = tid & 31, w = tid >> 5;
    int lm15 = lane & 15, l4 = lane >> 4, lr = lane >> 2, lc = (lane & 3) * 2;
    int bh = blockIdx.y, b = bh >> 4, h = bh & 15;
    int i0 = blockIdx.x * 128;
    int p1 = pm1[b], p2 = pm2[b];

    int rw = w * 16;
    int gi0 = i0 + rw + lr, gi1 = gi0 + 8;
    bool fm0 = (gi0 >= p2) || (p1 == 0);
    bool fm1 = (gi1 >= p2) || (p1 == 0);

    int jt_max = 0;
    if (!((i0 >= p2) || (p1 == 0))) {
        int J = min(i0 + 128, p1);
        jt_max = (J + 127) >> 7;
    }

    float po[8][4];
#pragma unroll
    for (int nb = 0; nb < 8; nb++)
#pragma unroll
        for (int r = 0; r < 4; r++) po[nb][r] = 0.f;
    float ls0 = 0.f, ls1 = 0.f;

    if (jt_max > 0) {
        {
            const char* qg = (const char*)(qs + ((size_t)bh * 1024 + i0) * 128);
#pragma unroll
            for (int i = 0; i < 8; i++) {
                int f = i * 256 + tid; int r = f >> 4, c = f & 15;
                asm volatile("cp.async.cg.shared.global [%0], [%1], 16;"
                    :: "r"(QS + r * ROWB + c * 16), "l"(qg + r * 256 + c * 16));
            }
            asm volatile("cp.async.commit_group;" ::: "memory");
        }
        {
            const char* kg = (const char*)(ks + (size_t)bh * 1024 * 128);
            const char* vg = (const char*)(vs + (size_t)bh * 1024 * 128);
            uint32_t KB = sb + TILEB, VB = sb + 2 * TILEB;
#pragma unroll
            for (int i = 0; i < 8; i++) {
                int f = i * 256 + tid; int r = f >> 4, c = f & 15;
                asm volatile("cp.async.cg.shared.global [%0], [%1], 16;"
                    :: "r"(KB + r * ROWB + c * 16), "l"(kg + r * 256 + c * 16));
                asm volatile("cp.async.cg.shared.global [%0], [%1], 16;"
                    :: "r"(VB + r * ROWB + c * 16), "l"(vg + r * 256 + c * 16));
            }
            asm volatile("cp.async.commit_group;" ::: "memory");
        }

        for (int jt = 0; jt < jt_max; jt++) {
            int j0 = jt * 128;
            if (jt + 1 < jt_max) {
                int jn = (jt + 1) & 1;
                uint32_t KB = sb + (1 + 2 * jn) * TILEB;
                uint32_t VB = KB + TILEB;
                const char* kg = (const char*)(ks + ((size_t)bh * 1024 + (jt + 1) * 128) * 128);
                const char* vg = (const char*)(vs + ((size_t)bh * 1024 + (jt + 1) * 128) * 128);
#pragma unroll
                for (int i = 0; i < 8; i++) {
                    int f = i * 256 + tid; int r = f >> 4, c = f & 15;
                    asm volatile("cp.async.cg.shared.global [%0], [%1], 16;"
                        :: "r"(KB + r * ROWB + c * 16), "l"(kg + r * 256 + c * 16));
                    asm volatile("cp.async.cg.shared.global [%0], [%1], 16;"
                        :: "r"(VB + r * ROWB + c * 16), "l"(vg + r * 256 + c * 16));
                }
                asm volatile("cp.async.commit_group;" ::: "memory");
                asm volatile("cp.async.wait_group 1;" ::: "memory");
            } else {
                asm volatile("cp.async.wait_group 0;" ::: "memory");
            }
            __syncthreads();

            uint32_t KS = sb + (1 + 2 * (jt & 1)) * TILEB;
            uint32_t VS = KS + TILEB;

            float sc[16][4];
#pragma unroll
            for (int nb = 0; nb < 16; nb++)
#pragma unroll
                for (int r = 0; r < 4; r++) sc[nb][r] = 0.f;

#pragma unroll
            for (int ks4 = 0; ks4 < 4; ks4++) {
                uint32_t a_hi[4], a_lo[4], bb_h[8][4], bb_l[8][4];
                int ch = 2 * ks4 + l4, cl = 8 + 2 * ks4 + l4;
                asm volatile("ldmatrix.sync.aligned.m8n8.x4.shared.b16 {%0,%1,%2,%3}, [%4];"
                    : "=r"(a_hi[0]), "=r"(a_hi[1]), "=r"(a_hi[2]), "=r"(a_hi[3])
                    : "r"(QS + (rw + lm15) * ROWB + ch * 16));
                asm volatile("ldmatrix.sync.aligned.m8n8.x4.shared.b16 {%0,%1,%2,%3}, [%4];"
                    : "=r"(a_lo[0]), "=r"(a_lo[1]), "=r"(a_lo[2]), "=r"(a_lo[3])
                    : "r"(QS + (rw + lm15) * ROWB + cl * 16));
#pragma unroll
                for (int g = 0; g < 8; g++) {
                    asm volatile("ldmatrix.sync.aligned.m8n8.x4.shared.b16 {%0,%1,%2,%3}, [%4];"
                        : "=r"(bb_h[g][0]), "=r"(bb_h[g][1]), "=r"(bb_h[g][2]), "=r"(bb_h[g][3])
                        : "r"(KS + (g * 16 + lm15) * ROWB + ch * 16));
                    asm volatile("ldmatrix.sync.aligned.m8n8.x4.shared.b16 {%0,%1,%2,%3}, [%4];"
                        : "=r"(bb_l[g][0]), "=r"(bb_l[g][1]), "=r"(bb_l[g][2]), "=r"(bb_l[g][3])
                        : "r"(KS + (g * 16 + lm15) * ROWB + cl * 16));
                }
#pragma unroll
                for (int nb = 0; nb < 16; nb++) {
                    uint32_t bh0 = bb_h[nb >> 1][nb & 1], bh1 = bb_h[nb >> 1][(nb & 1) + 2];
                    uint32_t bl0 = bb_l[nb >> 1][nb & 1], bl1 = bb_l[nb >> 1][(nb & 1) + 2];
                    asm volatile(
                        "mma.sync.aligned.m16n8k16.row.col.f32.bf16.bf16.f32 "
                        "{%0,%1,%2,%3}, {%4,%5,%6,%7}, {%8,%9}, {%0,%1,%2,%3};"
                        : "+f"(sc[nb][0]), "+f"(sc[nb][1]), "+f"(sc[nb][2]), "+f"(sc[nb][3])
                        : "r"(a_hi[0]), "r"(a_hi[1]), "r"(a_hi[2]), "r"(a_hi[3]), "r"(bh0), "r"(bh1));
                    asm volatile(
                        "mma.sync.aligned.m16n8k16.row.col.f32.bf16.bf16.f32 "
                        "{%0,%1,%2,%3}, {%4,%5,%6,%7}, {%8,%9}, {%0,%1,%2,%3};"
                        : "+f"(sc[nb][0]), "+f"(sc[nb][1]), "+f"(sc[nb][2]), "+f"(sc[nb][3])
                        : "r"(a_hi[0]), "r"(a_hi[1]), "r"(a_hi[2]), "r"(a_hi[3]), "r"(bl0), "r"(bl1));
                    asm volatile(
                        "mma.sync.aligned.m16n8k16.row.col.f32.bf16.bf16.f32 "
                        "{%0,%1,%2,%3}, {%4,%5,%6,%7}, {%8,%9}, {%0,%1,%2,%3};"
                        : "+f"(sc[nb][0]), "+f"(sc[nb][1]), "+f"(sc[nb][2]), "+f"(sc[nb][3])
                        : "r"(a_lo[0]), "r"(a_lo[1]), "r"(a_lo[2]), "r"(a_lo[3]), "r"(bh0), "r"(bh1));
                }
            }

            bool fullLive = (jt < blockIdx.x) && (j0 + 128 <= p1);
            if (fullLive) {
#pragma unroll
                for (int nb = 0; nb < 16; nb++) {
                    float v00 = __expf(sc[nb][0]);
                    float v01 = __expf(sc[nb][1]);
                    float v10 = __expf(sc[nb][2]);
                    float v11 = __expf(sc[nb][3]);
                    ls0 += v00 + v01;
                    ls1 += v10 + v11;
                    sc[nb][0] = v00; sc[nb][1] = v01; sc[nb][2] = v10; sc[nb][3] = v11;
                }
            } else {
                int t0 = fm0 ? 0 : min(gi0 + 1, p1);
                int t1 = fm1 ? 0 : min(gi1 + 1, p1);
#pragma unroll
                for (int nb = 0; nb < 16; nb++) {
                    int gj0 = j0 + nb * 8 + lc, gj1 = gj0 + 1;
                    float v00 = (gj0 < t0) ? __expf(sc[nb][0]) : 0.f;
                    float v01 = (gj1 < t0) ? __expf(sc[nb][1]) : 0.f;
                    float v10 = (gj0 < t1) ? __expf(sc[nb][2]) : 0.f;
                    float v11 = (gj1 < t1) ? __expf(sc[nb][3]) : 0.f;
                    ls0 += v00 + v01;
                    ls1 += v10 + v11;
                    sc[nb][0] = v00; sc[nb][1] = v01; sc[nb][2] = v10; sc[nb][3] = v11;
                }
            }

#pragma unroll
            for (int t = 0; t < 8; t++) {
                uint32_t ahi[4], alo[4];
#pragma unroll
                for (int half = 0; half < 2; half++) {
                    float* s4 = sc[2 * t + half];
                    __nv_bfloat16 h0 = __float2bfloat16(s4[0]), h1 = __float2bfloat16(s4[1]);
                    __nv_bfloat16 h2 = __float2bfloat16(s4[2]), h3 = __float2bfloat16(s4[3]);
                    ahi[half * 2]     = (uint32_t)__bfloat16_as_ushort(h0) | ((uint32_t)__bfloat16_as_ushort(h1) << 16);
                    ahi[half * 2 + 1] = (uint32_t)__bfloat16_as_ushort(h2) | ((uint32_t)__bfloat16_as_ushort(h3) << 16);
                    alo[half * 2]     = pack_bf2(s4[0] - __bfloat162float(h0), s4[1] - __bfloat162float(h1));
                    alo[half * 2 + 1] = pack_bf2(s4[2] - __bfloat162float(h2), s4[3] - __bfloat162float(h3));
                }
                uint32_t af_hi[4] = { ahi[0], ahi[1], ahi[2], ahi[3] };
                uint32_t af_lo[4] = { alo[0], alo[1], alo[2], alo[3] };

                uint32_t bth[4][4], btl[4][4];
#pragma unroll
                for (int db = 0; db < 4; db++) {
                    int rv = t * 16 + lm15;
                    asm volatile("ldmatrix.sync.aligned.m8n8.x4.trans.shared.b16 {%0,%1,%2,%3}, [%4];"
                        : "=r"(bth[db][0]), "=r"(bth[db][1]), "=r"(bth[db][2]), "=r"(bth[db][3])
                        : "r"(VS + rv * ROWB + (db * 2 + l4) * 16));
                    asm volatile("ldmatrix.sync.aligned.m8n8.x4.trans.shared.b16 {%0,%1,%2,%3}, [%4];"
                        : "=r"(btl[db][0]), "=r"(btl[db][1]), "=r"(btl[db][2]), "=r"(btl[db][3])
                        : "r"(VS + rv * ROWB + (8 + db * 2 + l4) * 16));
                }
#pragma unroll
                for (int db = 0; db < 4; db++)
#pragma unroll
                    for (int nf = 0; nf < 2; nf++) {
                        int nb = db * 2 + nf;
                        asm volatile(
                            "mma.sync.aligned.m16n8k16.row.col.f32.bf16.bf16.f32 "
                            "{%0,%1,%2,%3}, {%4,%5,%6,%7}, {%8,%9}, {%0,%1,%2,%3};"
                            : "+f"(po[nb][0]), "+f"(po[nb][1]), "+f"(po[nb][2]), "+f"(po[nb][3])
                            : "r"(af_hi[0]), "r"(af_hi[1]), "r"(af_hi[2]), "r"(af_hi[3]),
                              "r"(bth[db][nf * 2]), "r"(bth[db][nf * 2 + 1]));
                        asm volatile(
                            "mma.sync.aligned.m16n8k16.row.col.f32.bf16.bf16.f32 "
                            "{%0,%1,%2,%3}, {%4,%5,%6,%7}, {%8,%9}, {%0,%1,%2,%3};"
                            : "+f"(po[nb][0]), "+f"(po[nb][1]), "+f"(po[nb][2]), "+f"(po[nb][3])
                            : "r"(af_hi[0]), "r"(af_hi[1]), "r"(af_hi[2]), "r"(af_hi[3]),
                              "r"(btl[db][nf * 2]), "r"(btl[db][nf * 2 + 1]));
                        asm volatile(
                            "mma.sync.aligned.m16n8k16.row.col.f32.bf16.bf16.f32 "
                            "{%0,%1,%2,%3}, {%4,%5,%6,%7}, {%8,%9}, {%0,%1,%2,%3};"
                            : "+f"(po[nb][0]), "+f"(po[nb][1]), "+f"(po[nb][2]), "+f"(po[nb][3])
                            : "r"(af_lo[0]), "r"(af_lo[1]), "r"(af_lo[2]), "r"(af_lo[3]),
                              "r"(bth[db][nf * 2]), "r"(bth[db][nf * 2 + 1]));
                    }
            }
            __syncthreads();
        }
    }

    ls0 += __shfl_xor_sync(0xffffffffu, ls0, 1);
    ls0 += __shfl_xor_sync(0xffffffffu, ls0, 2);
    ls1 += __shfl_xor_sync(0xffffffffu, ls1, 1);
    ls1 += __shfl_xor_sync(0xffffffffu, ls1, 2);
    float inv0 = fm0 ? 0.f : 1.0f / ls0;
    float inv1 = fm1 ? 0.f : 1.0f / ls1;

    size_t mr0 = ((size_t)b * 1024 + (i0 + rw + lr)) * (size_t)KROW;
    size_t mr1 = ((size_t)b * 1024 + (i0 + rw + lr + 8)) * (size_t)KROW;
#pragma unroll
    for (int nb = 0; nb < 8; nb++) {
        int d = nb * 8 + lc;
        int col = h * 64 + d;
        float x0, x1, y0, y1;
        if (fm0) { x0 = vmean[bh * 64 + d]; x1 = vmean[bh * 64 + d + 1]; }
        else     { x0 = po[nb][0] * inv0;   x1 = po[nb][1] * inv0; }
        if (fm1) { y0 = vmean[bh * 64 + d]; y1 = vmean[bh * 64 + d + 1]; }
        else     { y0 = po[nb][2] * inv1;   y1 = po[nb][3] * inv1; }

        __nv_bfloat16 hx0 = __float2bfloat16(x0), hx1 = __float2bfloat16(x1);
        uint32_t hp0 = (uint32_t)__bfloat16_as_ushort(hx0) | ((uint32_t)__bfloat16_as_ushort(hx1) << 16);
        uint32_t lq0 = pack_bf2(x0 - __bfloat162float(hx0), x1 - __bfloat162float(hx1));
        __nv_bfloat16 hy0 = __float2bfloat16(y0), hy1 = __float2bfloat16(y1);
        uint32_t hp1 = (uint32_t)__bfloat16_as_ushort(hy0) | ((uint32_t)__bfloat16_as_ushort(hy1) << 16);
        uint32_t lq1 = pack_bf2(y0 - __bfloat162float(hy0), y1 - __bfloat162float(hy1));

        *(uint32_t*)(ap + mr0 + col)        = hp0;
        *(uint32_t*)(ap + mr0 + col + 1024) = lq0;
        *(uint32_t*)(ap + mr1 + col)        = hp1;
        *(uint32_t*)(ap + mr1 + col + 1024) = lq1;
    }
}

// ---------------------------------------------------------------------------
extern "C" void kernel_launch(void* const* d_in, const int* in_sizes, int n_in,
                              void* d_out, int out_size)
{
    const float* q   = (const float*)d_in[0];
    const float* k   = (const float*)d_in[1];
    const float* v   = (const float*)d_in[2];
    const int*   pm1 = (const int*)d_in[3];
    const int*   pm2 = (const int*)d_in[4];
    const float* Wq  = (const float*)d_in[5];
    const float* Wk  = (const float*)d_in[6];
    const float* Wv  = (const float*)d_in[7];
    const float* Wo  = (const float*)d_in[8];
    float* out = (float*)d_out;

    __nv_bfloat16 *qs, *ksp, *vsp, *ap, *wp;
    float *vbar, *vmean;
    cudaGetSymbolAddress((void**)&qs,    g_qs);
    cudaGetSymbolAddress((void**)&ksp,   g_ks);
    cudaGetSymbolAddress((void**)&vsp,   g_vs);
    cudaGetSymbolAddress((void**)&ap,    g_ap);
    cudaGetSymbolAddress((void**)&wp,    g_wp);
    cudaGetSymbolAddress((void**)&vbar,  g_vbar);
    cudaGetSymbolAddress((void**)&vmean, g_vmean);

    cudaFuncSetAttribute(gemm_mma,
        cudaFuncAttributeMaxDynamicSharedMemorySize, GEMM_SMEM);
    cudaFuncSetAttribute(attn_mma,
        cudaFuncAttributeMaxDynamicSharedMemorySize, AT_SMEM);

    // One launch: vbar + all W splits + all A splits (14848 CTAs)
    conv_mega<<<14848, 256>>>(q, k, v, Wq, Wk, Wv, Wo, ap, wp, vbar);
    vmean_small<<<Bc * Hc, 256>>>(Wv, vbar, vmean);

    // Merged q/k/v projection GEMMs (Q output pre-scaled by 0.125)
    gemm_mma<<<dim3(Dc / 256, Mrows / 128, 3), 256, GEMM_SMEM>>>(
        ap, wp, (void*)qs, (void*)ksp, (void*)vsp, 2);

    attn_mma<<<dim3(Sc / 128, Bc * Hc), 256, AT_SMEM>>>(qs, ksp, vsp, pm1, pm2, vmean, ap);

    gemm_mma<<<dim3(Dc / 256, Mrows / 128, 1), 256, GEMM_SMEM>>>(
        ap, wp + 3 * WSEC, (void*)out, (void*)out, (void*)out, 0);
}